// round 14
// baseline (speedup 1.0000x reference)
#include <cuda_runtime.h>
#include <cuda_bf16.h>
#include <math.h>
#include <stdint.h>

// ---------------- problem constants ----------------
#define BB 4
#define CC 128
#define HIMG 192
#define WIMG 192
#define PP (HIMG*WIMG)          // 36864
#define NH 2
#define HD 64
#define BNH (BB*NH)             // 8
#define NBX (PP/128)            // 288
#define NDW 9                   // dw blocks per plane (16 px/thread)
#define NCH2 72                 // gram chunks per (b,head)
#define CPX2 (PP/NCH2)          // 512

#define ELEMS ((size_t)BB*CC*PP)

// weight-split offsets (elements)
#define OWQ 0
#define OWK 16384
#define OWV 32768
#define OF1 49152
#define OF2 65536
#define OFO 81920
#define WTOT 114688

// ---------------- scratch ----------------
__device__ float g_t [ELEMS];
__device__ float g_t2[ELEMS];
__device__ float g_t3[ELEMS];
__device__ float g_q [ELEMS];   // attention: float q; FFN phase: ushort hi/lo planes (o1)
__device__ float g_k [ELEMS];   // attention: float k; FFN phase: ushort hi/lo planes (o2)
__device__ float g_v [ELEMS];
__device__ float g_part[(size_t)BNH*NCH2*HD*HD];
__device__ float g_a[BNH*HD*HD];
__device__ float g_sqq[BB*CC*NDW];
__device__ float g_sqk[BB*CC*NDW];
__device__ float g_psum[BB*CC*NBX];
__device__ float g_pmax[BB*CC*NBX];
__device__ unsigned short g_whi[WTOT];
__device__ unsigned short g_wlo[WTOT];

__device__ __forceinline__ float gelu_f(float x) {
    return 0.5f * x * (1.0f + erff(x * 0.70710678118654752f));
}

// ================= mma.sync helpers =================
__device__ __forceinline__ uint32_t smem_u32(const void* p) {
    uint32_t a;
    asm("{ .reg .u64 t; cvta.to.shared.u64 t, %1; cvt.u32.u64 %0, t; }" : "=r"(a) : "l"(p));
    return a;
}
__device__ __forceinline__ void ldsm_x4(uint32_t* r, uint32_t addr) {
    asm volatile("ldmatrix.sync.aligned.m8n8.x4.shared.b16 {%0,%1,%2,%3}, [%4];"
        : "=r"(r[0]), "=r"(r[1]), "=r"(r[2]), "=r"(r[3]) : "r"(addr));
}
__device__ __forceinline__ void ldsm_x4_t(uint32_t* r, uint32_t addr) {
    asm volatile("ldmatrix.sync.aligned.m8n8.x4.trans.shared.b16 {%0,%1,%2,%3}, [%4];"
        : "=r"(r[0]), "=r"(r[1]), "=r"(r[2]), "=r"(r[3]) : "r"(addr));
}
__device__ __forceinline__ void mma_bf16(float* c, const uint32_t* a, uint32_t b0, uint32_t b1) {
    asm volatile(
        "mma.sync.aligned.m16n8k16.row.col.f32.bf16.bf16.f32 "
        "{%0,%1,%2,%3}, {%4,%5,%6,%7}, {%8,%9}, {%0,%1,%2,%3};"
        : "+f"(c[0]), "+f"(c[1]), "+f"(c[2]), "+f"(c[3])
        : "r"(a[0]), "r"(a[1]), "r"(a[2]), "r"(a[3]), "r"(b0), "r"(b1));
}
__device__ __forceinline__ void split2(float x, float y, uint32_t& hi, uint32_t& lo) {
    __nv_bfloat16 hx = __float2bfloat16_rn(x);
    __nv_bfloat16 hy = __float2bfloat16_rn(y);
    __nv_bfloat16 lx = __float2bfloat16_rn(x - __bfloat162float(hx));
    __nv_bfloat16 ly = __float2bfloat16_rn(y - __bfloat162float(hy));
    hi = (uint32_t)__bfloat16_as_ushort(hx) | ((uint32_t)__bfloat16_as_ushort(hy) << 16);
    lo = (uint32_t)__bfloat16_as_ushort(lx) | ((uint32_t)__bfloat16_as_ushort(ly) << 16);
}

// ---------------- merged weight split precompute (one launch) ----------------
__global__ void wprep_all(const float* __restrict__ wq, const float* __restrict__ wk,
                          const float* __restrict__ wv, const float* __restrict__ f1,
                          const float* __restrict__ f2, const float* __restrict__ fo,
                          unsigned short* __restrict__ hi, unsigned short* __restrict__ lo) {
    int i = blockIdx.x * 256 + threadIdx.x;
    if (i >= WTOT) return;
    const float* src; int off;
    if (i < OWK)      { src = wq; off = OWQ; }
    else if (i < OWV) { src = wk; off = OWK; }
    else if (i < OF1) { src = wv; off = OWV; }
    else if (i < OF2) { src = f1; off = OF1; }
    else if (i < OFO) { src = f2; off = OF2; }
    else              { src = fo; off = OFO; }
    float x = src[i - off];
    __nv_bfloat16 h = __float2bfloat16_rn(x);
    __nv_bfloat16 l = __float2bfloat16_rn(x - __bfloat162float(h));
    hi[i] = __bfloat16_as_ushort(h);
    lo[i] = __bfloat16_as_ushort(l);
}

// ============== fused HMMA pointwise GEMM (split-M: 64x128 tile, 2 CTAs/SM) ==============
#define LDA 136
#define XT_BYTES (128*LDA*2)
#define WT_BYTES (64*LDA*2)
#define MM_SMEM  (2*XT_BYTES + 2*WT_BYTES)     // 104448
#define MM_SMEM_LN (MM_SMEM + (2048 + 256)*4)  // 113664

template<int KPASS, int NSET, bool LNIN, bool PRESPLIT, bool GOUT, bool POOL, bool STORE>
__global__ void __launch_bounds__(256, 2) gemm_fused(
    const unsigned short* __restrict__ WHI, const unsigned short* __restrict__ WLO,
    long wo0, long wo1, long wo2,
    const void* __restrict__ X0, const void* __restrict__ X1, long xstride,
    const float* __restrict__ lnw, const float* __restrict__ lnb,
    float* __restrict__ Y0, float* __restrict__ Y1, float* __restrict__ Y2, long ystride,
    float* __restrict__ psum, float* __restrict__ pmax)
{
    extern __shared__ __align__(16) char smem[];
    uint32_t sX_hi = smem_u32(smem);
    uint32_t sX_lo = sX_hi + XT_BYTES;
    uint32_t sW_hi = sX_lo + XT_BYTES;
    uint32_t sW_lo = sW_hi + WT_BYTES;
    float* statsS = (float*)(smem + MM_SMEM);
    float* statsQ = statsS + 1024;
    float* muS    = statsQ + 1024;
    float* rsS    = muS + 128;

    const int tid = threadIdx.x;
    const int wid = tid >> 5, lane = tid & 31;
    const int bi = blockIdx.z;
    const int mh = blockIdx.y;
    const int p0 = blockIdx.x * 128;

    const int wm = wid & 1, wn = wid >> 1;
    const int m0 = wm * 32, n0 = wn * 32;
    const int ar = (lane & 7) + ((lane >> 3) & 1) * 8;
    const int ac = ((lane >> 4) & 1) * 8;
    const uint32_t offW = (uint32_t)((m0 + ar) * LDA + ac) * 2;
    const uint32_t offX = (uint32_t)(ar * LDA + n0 + ac) * 2;

    float C[2][4][4];
    if (KPASS > 1) {
        #pragma unroll
        for (int mt = 0; mt < 2; mt++)
            #pragma unroll
            for (int nt = 0; nt < 4; nt++)
                #pragma unroll
                for (int e = 0; e < 4; e++) C[mt][nt][e] = 0.f;
    }

    const int WROW = 128 * KPASS;

    #pragma unroll
    for (int pass = 0; pass < KPASS; pass++) {
        if (pass > 0) __syncthreads();

        if (PRESPLIT) {
            const unsigned short* Xh =
                (const unsigned short*)((pass == 0) ? X0 : X1) + (long)bi * xstride;
            const unsigned short* Xl = Xh + ELEMS;
            #pragma unroll
            for (int it = 0; it < 16; it++) {
                int idx = (it * 256 + tid) * 4;
                int kk = idx >> 7, nn = idx & 127;
                long src = (long)kk * PP + p0 + nn;
                uint2 h = *(const uint2*)&Xh[src];
                uint2 l = *(const uint2*)&Xl[src];
                uint32_t off = (uint32_t)(kk * LDA + nn) * 2;
                asm volatile("st.shared.v2.b32 [%0], {%1,%2};" :: "r"(sX_hi + off), "r"(h.x), "r"(h.y));
                asm volatile("st.shared.v2.b32 [%0], {%1,%2};" :: "r"(sX_lo + off), "r"(l.x), "r"(l.y));
            }
        } else {
            const float* Xsrc = (const float*)((pass == 0) ? X0 : X1) + (long)bi * xstride;
            if (LNIN) {
                float4 s4 = make_float4(0.f,0.f,0.f,0.f), q4 = make_float4(0.f,0.f,0.f,0.f);
                #pragma unroll
                for (int it = 0; it < 16; it++) {
                    int idx = (it * 256 + tid) * 4;
                    int kk = idx >> 7, nn = idx & 127;
                    float4 v = *(const float4*)&Xsrc[(long)kk * PP + p0 + nn];
                    s4.x += v.x; s4.y += v.y; s4.z += v.z; s4.w += v.w;
                    q4.x += v.x*v.x; q4.y += v.y*v.y; q4.z += v.z*v.z; q4.w += v.w*v.w;
                }
                {
                    int nn = (tid & 31) * 4;
                    *(float4*)&statsS[wid * 128 + nn] = s4;
                    *(float4*)&statsQ[wid * 128 + nn] = q4;
                }
                __syncthreads();
                if (tid < 128) {
                    float s = 0.f, q2 = 0.f;
                    #pragma unroll
                    for (int g = 0; g < 8; g++) { s += statsS[g * 128 + tid]; q2 += statsQ[g * 128 + tid]; }
                    float mu = s * (1.0f / 128.0f);
                    float var = q2 * (1.0f / 128.0f) - mu * mu;
                    muS[tid] = mu;
                    rsS[tid] = rsqrtf(var + 1e-5f);
                }
                __syncthreads();
                #pragma unroll
                for (int it = 0; it < 16; it++) {
                    int idx = (it * 256 + tid) * 4;
                    int kk = idx >> 7, nn = idx & 127;
                    float4 v = *(const float4*)&Xsrc[(long)kk * PP + p0 + nn];
                    float wc = __ldg(&lnw[kk]), bc = __ldg(&lnb[kk]);
                    v.x = (v.x - muS[nn + 0]) * rsS[nn + 0] * wc + bc;
                    v.y = (v.y - muS[nn + 1]) * rsS[nn + 1] * wc + bc;
                    v.z = (v.z - muS[nn + 2]) * rsS[nn + 2] * wc + bc;
                    v.w = (v.w - muS[nn + 3]) * rsS[nn + 3] * wc + bc;
                    uint32_t h0, l0, h1, l1;
                    split2(v.x, v.y, h0, l0);
                    split2(v.z, v.w, h1, l1);
                    uint32_t off = (uint32_t)(kk * LDA + nn) * 2;
                    asm volatile("st.shared.v2.b32 [%0], {%1,%2};" :: "r"(sX_hi + off), "r"(h0), "r"(h1));
                    asm volatile("st.shared.v2.b32 [%0], {%1,%2};" :: "r"(sX_lo + off), "r"(l0), "r"(l1));
                }
            } else {
                #pragma unroll
                for (int it = 0; it < 16; it++) {
                    int idx = (it * 256 + tid) * 4;
                    int kk = idx >> 7, nn = idx & 127;
                    float4 v = *(const float4*)&Xsrc[(long)kk * PP + p0 + nn];
                    uint32_t h0, l0, h1, l1;
                    split2(v.x, v.y, h0, l0);
                    split2(v.z, v.w, h1, l1);
                    uint32_t off = (uint32_t)(kk * LDA + nn) * 2;
                    asm volatile("st.shared.v2.b32 [%0], {%1,%2};" :: "r"(sX_hi + off), "r"(h0), "r"(h1));
                    asm volatile("st.shared.v2.b32 [%0], {%1,%2};" :: "r"(sX_lo + off), "r"(l0), "r"(l1));
                }
            }
        }

        #pragma unroll
        for (int s = 0; s < NSET; s++) {
            if (pass > 0 || s > 0) __syncthreads();
            const long wo = (s == 0) ? wo0 : ((s == 1) ? wo1 : wo2);
            #pragma unroll
            for (int it = 0; it < 8; it++) {
                int idx = (it * 256 + tid) * 4;
                int co = idx >> 7, k = idx & 127;
                long src = wo + (long)(mh * 64 + co) * WROW + pass * 128 + k;
                uint2 h = *(const uint2*)&WHI[src];
                uint2 l = *(const uint2*)&WLO[src];
                uint32_t off = (uint32_t)(co * LDA + k) * 2;
                asm volatile("st.shared.v2.b32 [%0], {%1,%2};" :: "r"(sW_hi + off), "r"(h.x), "r"(h.y));
                asm volatile("st.shared.v2.b32 [%0], {%1,%2};" :: "r"(sW_lo + off), "r"(l.x), "r"(l.y));
            }
            __syncthreads();

            if (KPASS == 1) {
                #pragma unroll
                for (int mt = 0; mt < 2; mt++)
                    #pragma unroll
                    for (int nt = 0; nt < 4; nt++)
                        #pragma unroll
                        for (int e = 0; e < 4; e++) C[mt][nt][e] = 0.f;
            }

            #pragma unroll
            for (int kk = 0; kk < 8; kk++) {
                int k0 = kk * 16;
                uint32_t ah[2][4], al[2][4];
                #pragma unroll
                for (int mt = 0; mt < 2; mt++) {
                    uint32_t o = offW + (uint32_t)(mt * 16 * LDA + k0) * 2;
                    ldsm_x4(ah[mt], sW_hi + o);
                    ldsm_x4(al[mt], sW_lo + o);
                }
                uint32_t bh[2][4], bl[2][4];
                #pragma unroll
                for (int bt = 0; bt < 2; bt++) {
                    uint32_t o = offX + (uint32_t)(k0 * LDA + bt * 16) * 2;
                    ldsm_x4_t(bh[bt], sX_hi + o);
                    ldsm_x4_t(bl[bt], sX_lo + o);
                }
                #pragma unroll
                for (int mt = 0; mt < 2; mt++)
                    #pragma unroll
                    for (int nt = 0; nt < 4; nt++) {
                        uint32_t b0h = bh[nt >> 1][(nt & 1) * 2], b1h = bh[nt >> 1][(nt & 1) * 2 + 1];
                        uint32_t b0l = bl[nt >> 1][(nt & 1) * 2], b1l = bl[nt >> 1][(nt & 1) * 2 + 1];
                        mma_bf16(C[mt][nt], ah[mt], b0h, b1h);
                        mma_bf16(C[mt][nt], ah[mt], b0l, b1l);
                        mma_bf16(C[mt][nt], al[mt], b0h, b1h);
                    }
            }

            if (KPASS == 1 && STORE) {
                float* Yb = ((s == 0) ? Y0 : ((s == 1) ? Y1 : Y2)) + (long)bi * ystride;
                const int g = lane >> 2, i2 = (lane & 3) * 2;
                #pragma unroll
                for (int mt = 0; mt < 2; mt++) {
                    int row0 = mh * 64 + m0 + mt * 16 + g;
                    #pragma unroll
                    for (int nt = 0; nt < 4; nt++) {
                        int p = p0 + n0 + nt * 8 + i2;
                        float2 o0 = make_float2(C[mt][nt][0], C[mt][nt][1]);
                        float2 o1 = make_float2(C[mt][nt][2], C[mt][nt][3]);
                        if (GOUT) {
                            o0.x = gelu_f(o0.x); o0.y = gelu_f(o0.y);
                            o1.x = gelu_f(o1.x); o1.y = gelu_f(o1.y);
                        }
                        *(float2*)&Yb[(long)row0 * PP + p]       = o0;
                        *(float2*)&Yb[(long)(row0 + 8) * PP + p] = o1;
                    }
                }
            }
        }
    }

    if (POOL) {
        __syncthreads();
        float* ps = (float*)smem;
        float* pm = ps + 256;
        const int g = lane >> 2;
        #pragma unroll
        for (int mt = 0; mt < 2; mt++) {
            float s0 = 0.f, s1 = 0.f, m0v = -INFINITY, m1v = -INFINITY;
            #pragma unroll
            for (int nt = 0; nt < 4; nt++) {
                s0 += C[mt][nt][0] + C[mt][nt][1];
                m0v = fmaxf(m0v, fmaxf(C[mt][nt][0], C[mt][nt][1]));
                s1 += C[mt][nt][2] + C[mt][nt][3];
                m1v = fmaxf(m1v, fmaxf(C[mt][nt][2], C[mt][nt][3]));
            }
            #pragma unroll
            for (int o = 1; o <= 2; o <<= 1) {
                s0 += __shfl_xor_sync(0xffffffffu, s0, o);
                s1 += __shfl_xor_sync(0xffffffffu, s1, o);
                m0v = fmaxf(m0v, __shfl_xor_sync(0xffffffffu, m0v, o));
                m1v = fmaxf(m1v, __shfl_xor_sync(0xffffffffu, m1v, o));
            }
            if ((lane & 3) == 0) {
                int r0 = m0 + mt * 16 + g;
                ps[r0 * 4 + wn] = s0;       pm[r0 * 4 + wn] = m0v;
                ps[(r0 + 8) * 4 + wn] = s1; pm[(r0 + 8) * 4 + wn] = m1v;
            }
        }
        __syncthreads();
        if (tid < 64) {
            float s = ps[tid*4] + ps[tid*4+1] + ps[tid*4+2] + ps[tid*4+3];
            float m = fmaxf(fmaxf(pm[tid*4], pm[tid*4+1]), fmaxf(pm[tid*4+2], pm[tid*4+3]));
            long ch = (long)(bi * CC + mh * 64 + tid);
            psum[ch * NBX + blockIdx.x] = s;
            pmax[ch * NBX + blockIdx.x] = m;
        }
    }
}

// ---------------- multi-tensor depthwise 3x3 pad 1: 4x4 px/thread ----------------
template<int SQMASK, bool GSPLIT>
__global__ void __launch_bounds__(256) dwm_kernel(
    const float* __restrict__ x0, const float* __restrict__ x1, const float* __restrict__ x2,
    const float* __restrict__ w0, const float* __restrict__ w1, const float* __restrict__ w2,
    void* __restrict__ y0, void* __restrict__ y1, void* __restrict__ y2,
    float* __restrict__ sq0, float* __restrict__ sq1) {
    int i = blockIdx.x * 256 + threadIdx.x;
    int bc = blockIdx.y;
    int z  = blockIdx.z;
    const float* x = (z == 0) ? x0 : ((z == 1) ? x1 : x2);
    const float* w = (z == 0) ? w0 : ((z == 1) ? w1 : w2);
    void* yout     = (z == 0) ? y0 : ((z == 1) ? y1 : y2);
    const bool doSQ = (SQMASK >> z) & 1;

    int rq = i / 48, cg = i % 48;
    int y0r = rq * 4, xx = cg * 4;
    const float* xp = x + (size_t)bc * PP;
    const float* wc = w + (bc % CC) * 9;
    float kw[3][3];
    #pragma unroll
    for (int j = 0; j < 9; j++) kw[j/3][j%3] = wc[j];

    float4 c[6]; float lf[6], rt[6];
    #pragma unroll
    for (int r = 0; r < 6; r++) {
        int sy = y0r - 1 + r;
        bool ok = (unsigned)sy < HIMG;
        const float* row = xp + sy * WIMG + xx;
        c[r]  = ok ? *(const float4*)row : make_float4(0.f, 0.f, 0.f, 0.f);
        lf[r] = (ok && xx > 0) ? row[-1] : 0.f;
        rt[r] = (ok && xx + 4 < WIMG) ? row[4] : 0.f;
    }

    float4 a[4];
    #pragma unroll
    for (int r = 0; r < 4; r++) a[r] = make_float4(0.f, 0.f, 0.f, 0.f);
    #pragma unroll
    for (int ky = 0; ky < 3; ky++) {
        float k0 = kw[ky][0], k1 = kw[ky][1], k2 = kw[ky][2];
        #pragma unroll
        for (int r = 0; r < 4; r++) {
            float4 cc = c[r + ky]; float l = lf[r + ky], rr = rt[r + ky];
            a[r].x += k0*l    + k1*cc.x + k2*cc.y;
            a[r].y += k0*cc.x + k1*cc.y + k2*cc.z;
            a[r].z += k0*cc.y + k1*cc.z + k2*cc.w;
            a[r].w += k0*cc.z + k1*cc.w + k2*rr;
        }
    }

    if (GSPLIT) {
        unsigned short* yh = (unsigned short*)yout;
        unsigned short* yl = yh + ELEMS;
        #pragma unroll
        for (int r = 0; r < 4; r++) {
            float gx = gelu_f(a[r].x), gy = gelu_f(a[r].y);
            float gz = gelu_f(a[r].z), gw = gelu_f(a[r].w);
            uint32_t h0, l0, h1, l1;
            split2(gx, gy, h0, l0);
            split2(gz, gw, h1, l1);
            size_t o = (size_t)bc * PP + (y0r + r) * WIMG + xx;
            *(uint2*)&yh[o] = make_uint2(h0, h1);
            *(uint2*)&yl[o] = make_uint2(l0, l1);
        }
    } else {
        float* yp = (float*)yout + (size_t)bc * PP;
        #pragma unroll
        for (int r = 0; r < 4; r++)
            *(float4*)&yp[(y0r + r) * WIMG + xx] = a[r];
    }

    if (SQMASK) {
        if (doSQ) {
            float s = 0.f;
            #pragma unroll
            for (int r = 0; r < 4; r++)
                s += a[r].x*a[r].x + a[r].y*a[r].y + a[r].z*a[r].z + a[r].w*a[r].w;
            __shared__ float red[256];
            red[threadIdx.x] = s; __syncthreads();
            for (int o = 128; o > 0; o >>= 1) {
                if (threadIdx.x < o) red[threadIdx.x] += red[threadIdx.x + o];
                __syncthreads();
            }
            if (threadIdx.x == 0) {
                float* sqp = (z == 0) ? sq0 : sq1;
                sqp[bc * NDW + blockIdx.x] = red[0];
            }
        }
    }
}

// ---------------- Gram partials via HMMA (bf16 split, 2 CTAs/SM) ----------------
#define LDK 136
#define GT_BYTES (64*LDK*2)
#define GR_SMEM (4*GT_BYTES)
__global__ void __launch_bounds__(256, 2) gram_mma(const float* __restrict__ q,
                                                   const float* __restrict__ k,
                                                   float* __restrict__ part) {
    extern __shared__ __align__(16) char smem[];
    uint32_t sb = smem_u32(smem);
    uint32_t sQ_hi = sb, sQ_lo = sb + GT_BYTES;
    uint32_t sK_hi = sb + 2*GT_BYTES, sK_lo = sb + 3*GT_BYTES;

    const int tid = threadIdx.x;
    const int wid = tid >> 5, lane = tid & 31;
    const int ch = blockIdx.x, bn = blockIdx.y;
    const float* qb = q + (size_t)bn * HD * PP + ch * CPX2;
    const float* kb = k + (size_t)bn * HD * PP + ch * CPX2;

    const int wm = wid & 1, wn = wid >> 1;
    const int m0 = wm * 32, n0 = wn * 16;
    const int ar = (lane & 7) + ((lane >> 3) & 1) * 8;
    const int ac = ((lane >> 4) & 1) * 8;
    const uint32_t offA = (uint32_t)((m0 + ar) * LDK + ac) * 2;
    const uint32_t offB = (uint32_t)((n0 + ar) * LDK + ac) * 2;

    float C[2][2][4];
    #pragma unroll
    for (int mt = 0; mt < 2; mt++)
        #pragma unroll
        for (int nt = 0; nt < 2; nt++)
            #pragma unroll
            for (int e = 0; e < 4; e++) C[mt][nt][e] = 0.f;

    for (int t = 0; t < CPX2 / 128; t++) {
        if (t > 0) __syncthreads();
        #pragma unroll
        for (int it = 0; it < 8; it++) {
            int idx = (it * 256 + tid) * 4;
            int r = idx >> 7, n = idx & 127;
            float4 v = *(const float4*)&qb[(size_t)r * PP + t * 128 + n];
            uint32_t h0, l0, h1, l1;
            split2(v.x, v.y, h0, l0); split2(v.z, v.w, h1, l1);
            uint32_t off = (uint32_t)(r * LDK + n) * 2;
            asm volatile("st.shared.v2.b32 [%0], {%1,%2};" :: "r"(sQ_hi + off), "r"(h0), "r"(h1));
            asm volatile("st.shared.v2.b32 [%0], {%1,%2};" :: "r"(sQ_lo + off), "r"(l0), "r"(l1));
        }
        #pragma unroll
        for (int it = 0; it < 8; it++) {
            int idx = (it * 256 + tid) * 4;
            int r = idx >> 7, n = idx & 127;
            float4 v = *(const float4*)&kb[(size_t)r * PP + t * 128 + n];
            uint32_t h0, l0, h1, l1;
            split2(v.x, v.y, h0, l0); split2(v.z, v.w, h1, l1);
            uint32_t off = (uint32_t)(r * LDK + n) * 2;
            asm volatile("st.shared.v2.b32 [%0], {%1,%2};" :: "r"(sK_hi + off), "r"(h0), "r"(h1));
            asm volatile("st.shared.v2.b32 [%0], {%1,%2};" :: "r"(sK_lo + off), "r"(l0), "r"(l1));
        }
        __syncthreads();

        #pragma unroll
        for (int kk = 0; kk < 8; kk++) {
            int k0 = kk * 16;
            uint32_t ah[2][4], al[2][4];
            #pragma unroll
            for (int mt = 0; mt < 2; mt++) {
                uint32_t o = offA + (uint32_t)(mt * 16 * LDK + k0) * 2;
                ldsm_x4(ah[mt], sQ_hi + o);
                ldsm_x4(al[mt], sQ_lo + o);
            }
            uint32_t bh[4], bl[4];
            ldsm_x4(bh, sK_hi + offB + (uint32_t)k0 * 2);
            ldsm_x4(bl, sK_lo + offB + (uint32_t)k0 * 2);
            #pragma unroll
            for (int mt = 0; mt < 2; mt++) {
                mma_bf16(C[mt][0], ah[mt], bh[0], bh[2]);
                mma_bf16(C[mt][1], ah[mt], bh[1], bh[3]);
                mma_bf16(C[mt][0], ah[mt], bl[0], bl[2]);
                mma_bf16(C[mt][1], ah[mt], bl[1], bl[3]);
                mma_bf16(C[mt][0], al[mt], bh[0], bh[2]);
                mma_bf16(C[mt][1], al[mt], bh[1], bh[3]);
            }
        }
    }

    float* pb = part + (((size_t)bn * NCH2 + ch) * HD) * HD;
    const int g = lane >> 2, i2 = (lane & 3) * 2;
    #pragma unroll
    for (int mt = 0; mt < 2; mt++) {
        int i = m0 + mt * 16 + g;
        #pragma unroll
        for (int nt = 0; nt < 2; nt++) {
            int j = n0 + nt * 8 + i2;
            pb[i * HD + j]       = C[mt][nt][0];
            pb[i * HD + j + 1]   = C[mt][nt][1];
            pb[(i + 8) * HD + j]     = C[mt][nt][2];
            pb[(i + 8) * HD + j + 1] = C[mt][nt][3];
        }
    }
}

// ---------------- norms (from dw sumsq partials) + reduce + softmax ----------------
__global__ void attn_softmax(const float* __restrict__ part,
                             const float* __restrict__ sqq, const float* __restrict__ sqk,
                             const float* __restrict__ scale,
                             float* __restrict__ attnw_out, float* __restrict__ a) {
    __shared__ float nqS[HD], nkS[HD];
    int bn = blockIdx.x;
    int n = bn % NH;
    int tid = threadIdx.x;
    int warp = tid / 32, lane = tid % 32;

    if (tid < 128) {
        int i = tid & 63;
        const float* sp = (tid < 64) ? sqq : sqk;
        float s = 0.f;
        #pragma unroll
        for (int j = 0; j < NDW; j++) s += sp[(bn * HD + i) * NDW + j];
        float nv = fmaxf(sqrtf(s), 1e-12f);
        if (tid < 64) nqS[i] = nv; else nkS[i] = nv;
    }
    __syncthreads();

    float sc = scale[n];
    for (int i = warp; i < HD; i += 8) {
        float v[2];
        #pragma unroll
        for (int h = 0; h < 2; h++) {
            int j = lane + 32 * h;
            float s = 0.f;
            for (int ch = 0; ch < NCH2; ch++)
                s += part[(((size_t)bn * NCH2 + ch) * HD + i) * HD + j];
            s = s * sc / (nqS[i] * nkS[j]);
            attnw_out[((size_t)bn * HD + i) * HD + j] = s;
            v[h] = s;
        }
        float m = fmaxf(v[0], v[1]);
        #pragma unroll
        for (int o = 16; o; o >>= 1) m = fmaxf(m, __shfl_xor_sync(0xffffffffu, m, o));
        float e0 = expf(v[0] - m), e1 = expf(v[1] - m);
        float s = e0 + e1;
        #pragma unroll
        for (int o = 16; o; o >>= 1) s += __shfl_xor_sync(0xffffffffu, s, o);
        float inv = 1.0f / s;
        a[((size_t)bn * HD + i) * HD + lane]      = e0 * inv;
        a[((size_t)bn * HD + i) * HD + lane + 32] = e1 * inv;
    }
}

// ---------------- fused a@v + channel-LN ----------------
#define AV_SMEM (8192*4 + 128*132*4 + (2*1024 + 256)*4)
__global__ void __launch_bounds__(256) avln_kernel(
    const float* __restrict__ a, const float* __restrict__ v,
    const float* __restrict__ lnw, const float* __restrict__ lnb,
    float* __restrict__ t)
{
    extern __shared__ __align__(16) float dsm[];
    float* As = dsm;
    float* Vs = As + 8192;
    float* redS = Vs + 128*132;
    float* redQ = redS + 1024;
    float* muA  = redQ + 1024;
    float* rsA  = muA + 128;

    const int tid = threadIdx.x;
    const int bi = blockIdx.y;
    const int p0 = blockIdx.x * 128;

    const float* ab = a + (size_t)bi * 2 * 4096;
    #pragma unroll
    for (int it = 0; it < 8; it++) {
        int idx = (it * 256 + tid) * 4;
        *(float4*)&As[idx] = *(const float4*)&ab[idx];
    }
    const float* vb = v + (size_t)bi * CC * PP;
    #pragma unroll
    for (int it = 0; it < 16; it++) {
        int idx = it * 256 + tid;
        int row = idx >> 5, n4 = idx & 31;
        *(float4*)&Vs[row * 132 + n4 * 4] = *(const float4*)&vb[(size_t)row * PP + p0 + n4 * 4];
    }
    __syncthreads();

    const int px4 = tid & 31;
    const int cg = tid >> 5;
    const int h = cg >> 2;
    const int cbase = cg * 16;
    const float* Ah = As + h * 4096;

    float4 acc[16];
    #pragma unroll
    for (int cl = 0; cl < 16; cl++) acc[cl] = make_float4(0.f, 0.f, 0.f, 0.f);

    #pragma unroll
    for (int j4 = 0; j4 < 16; j4++) {
        float4 vv0 = *(float4*)&Vs[(h*64 + j4*4 + 0) * 132 + px4*4];
        float4 vv1 = *(float4*)&Vs[(h*64 + j4*4 + 1) * 132 + px4*4];
        float4 vv2 = *(float4*)&Vs[(h*64 + j4*4 + 2) * 132 + px4*4];
        float4 vv3 = *(float4*)&Vs[(h*64 + j4*4 + 3) * 132 + px4*4];
        #pragma unroll
        for (int cl = 0; cl < 16; cl++) {
            int i = (cbase + cl) & 63;
            float4 a4 = *(float4*)&Ah[i * 64 + j4 * 4];
            acc[cl].x += a4.x*vv0.x + a4.y*vv1.x + a4.z*vv2.x + a4.w*vv3.x;
            acc[cl].y += a4.x*vv0.y + a4.y*vv1.y + a4.z*vv2.y + a4.w*vv3.y;
            acc[cl].z += a4.x*vv0.z + a4.y*vv1.z + a4.z*vv2.z + a4.w*vv3.z;
            acc[cl].w += a4.x*vv0.w + a4.y*vv1.w + a4.z*vv2.w + a4.w*vv3.w;
        }
    }

    float4 s4 = make_float4(0.f,0.f,0.f,0.f), q4 = make_float4(0.f,0.f,0.f,0.f);
    #pragma unroll
    for (int cl = 0; cl < 16; cl++) {
        s4.x += acc[cl].x; s4.y += acc[cl].y; s4.z += acc[cl].z; s4.w += acc[cl].w;
        q4.x += acc[cl].x*acc[cl].x; q4.y += acc[cl].y*acc[cl].y;
        q4.z += acc[cl].z*acc[cl].z; q4.w += acc[cl].w*acc[cl].w;
    }
    *(float4*)&redS[cg * 128 + px4 * 4] = s4;
    *(float4*)&redQ[cg * 128 + px4 * 4] = q4;
    __syncthreads();
    if (tid < 128) {
        float s = 0.f, q2 = 0.f;
        #pragma unroll
        for (int g = 0; g < 8; g++) { s += redS[g * 128 + tid]; q2 += redQ[g * 128 + tid]; }
        float mu = s * (1.0f / 128.0f);
        float var = q2 * (1.0f / 128.0f) - mu * mu;
        muA[tid] = mu;
        rsA[tid] = rsqrtf(var + 1e-5f);
    }
    __syncthreads();

    float4 mu4 = *(float4*)&muA[px4 * 4];
    float4 rs4 = *(float4*)&rsA[px4 * 4];
    float* tb = t + (size_t)bi * CC * PP;
    #pragma unroll
    for (int cl = 0; cl < 16; cl++) {
        int c = cbase + cl;
        float w = __ldg(&lnw[c]), b = __ldg(&lnb[c]);
        float4 o;
        o.x = (acc[cl].x - mu4.x) * rs4.x * w + b;
        o.y = (acc[cl].y - mu4.y) * rs4.y * w + b;
        o.z = (acc[cl].z - mu4.z) * rs4.z * w + b;
        o.w = (acc[cl].w - mu4.w) * rs4.w * w + b;
        *(float4*)&tb[(size_t)c * PP + p0 + px4 * 4] = o;
    }
}

// ---------------- pool partial reduce + ChannelGate ----------------
__global__ void gate_pool_kernel(const float* __restrict__ psum, const float* __restrict__ pmax,
                                 const float* __restrict__ w1, const float* __restrict__ b1,
                                 const float* __restrict__ w2, const float* __restrict__ b2,
                                 float* __restrict__ out) {
    __shared__ float sa[CC], sm_[CC], ha[8], hm[8];
    int c = threadIdx.x;
    for (int b = 0; b < BB; b++) {
        float s = 0.f, m = -INFINITY;
        long base = (long)(b * CC + c) * NBX;
        for (int i = 0; i < NBX; i++) {
            s += psum[base + i];
            m = fmaxf(m, pmax[base + i]);
        }
        sa[c] = s * (1.0f / PP);
        sm_[c] = m;
        __syncthreads();
        if (c < 8) {
            float xa = b1[c], xm = b1[c];
            for (int cc = 0; cc < CC; cc++) {
                xa += w1[c*CC + cc] * sa[cc];
                xm += w1[c*CC + cc] * sm_[cc];
            }
            ha[c] = fmaxf(xa, 0.f);
            hm[c] = fmaxf(xm, 0.f);
        }
        __syncthreads();
        float xa = b2[c], xm = b2[c];
        #pragma unroll
        for (int j = 0; j < 8; j++) {
            xa += w2[c*8 + j] * ha[j];
            xm += w2[c*8 + j] * hm[j];
        }
        out[b*CC + c] = 1.0f / (1.0f + expf(-(xa + xm)));
        __syncthreads();
    }
}

// ---------------- host launch ----------------
static float* sym(const void* s) {
    void* p = nullptr;
    cudaGetSymbolAddress(&p, s);
    return (float*)p;
}

extern "C" void kernel_launch(void* const* d_in, const int* in_sizes, int n_in,
                              void* d_out, int out_size) {
    const float* x       = (const float*)d_in[0];
    const float* ln_in_w = (const float*)d_in[1];
    const float* ln_in_b = (const float*)d_in[2];
    const float* wq_pw   = (const float*)d_in[3];
    const float* wq_dw   = (const float*)d_in[4];
    const float* wk_pw   = (const float*)d_in[5];
    const float* wk_dw   = (const float*)d_in[6];
    const float* wv_pw   = (const float*)d_in[7];
    const float* wv_dw   = (const float*)d_in[8];
    const float* scale   = (const float*)d_in[9];
    const float* ln_o_w  = (const float*)d_in[10];
    const float* ln_o_b  = (const float*)d_in[11];
    const float* f1_pw   = (const float*)d_in[12];
    const float* f1_dw   = (const float*)d_in[13];
    const float* f2_pw   = (const float*)d_in[14];
    const float* f2_dw   = (const float*)d_in[15];
    const float* f_out   = (const float*)d_in[16];
    const float* g_w1    = (const float*)d_in[17];
    const float* g_b1    = (const float*)d_in[18];
    const float* g_w2    = (const float*)d_in[19];
    const float* g_b2    = (const float*)d_in[20];
    float* out = (float*)d_out;

    float* t  = sym(g_t);   float* t2 = sym(g_t2);  float* t3 = sym(g_t3);
    float* q  = sym(g_q);   float* k  = sym(g_k);   float* v  = sym(g_v);
    float* part = sym(g_part); float* a = sym(g_a);
    float* sqq = sym(g_sqq);   float* sqk = sym(g_sqk);
    float* psum = sym(g_psum); float* pmax = sym(g_pmax);
    unsigned short* whi = (unsigned short*)sym(g_whi);
    unsigned short* wlo = (unsigned short*)sym(g_wlo);

    auto qkv  = gemm_fused<1,3,true, false,false,false,true>;
    auto f1f2 = gemm_fused<1,2,false,false,true, false,true>;
    auto fout = gemm_fused<2,1,false,true, false,true, false>;
    cudaFuncSetAttribute(qkv,  cudaFuncAttributeMaxDynamicSharedMemorySize, MM_SMEM_LN);
    cudaFuncSetAttribute(f1f2, cudaFuncAttributeMaxDynamicSharedMemorySize, MM_SMEM);
    cudaFuncSetAttribute(fout, cudaFuncAttributeMaxDynamicSharedMemorySize, MM_SMEM);
    cudaFuncSetAttribute(gram_mma, cudaFuncAttributeMaxDynamicSharedMemorySize, GR_SMEM);
    cudaFuncSetAttribute(avln_kernel, cudaFuncAttributeMaxDynamicSharedMemorySize, AV_SMEM);

    const long SB = (long)CC * PP;
    dim3 gGrid(NBX, 2, BB);
    dim3 dwGrid3(NDW, BB*CC, 3);
    dim3 dwGrid2(NDW, BB*CC, 2);
    dim3 avGrid(NBX, BB);

    // 0) precompute weight hi/lo splits (single merged launch)
    wprep_all<<<(WTOT + 255)/256, 256>>>(wq_pw, wk_pw, wv_pw, f1_pw, f2_pw, f_out, whi, wlo);

    // 1) fused LN + QKV pointwise
    qkv<<<gGrid, 256, MM_SMEM_LN>>>(whi, wlo, OWQ, OWK, OWV, x, nullptr, SB,
                                    ln_in_w, ln_in_b, t, t2, t3, SB, nullptr, nullptr);
    // 2) depthwise q/k/v in ONE launch (+ sumsq partials for q,k)
    dwm_kernel<3, false><<<dwGrid3, 256>>>(t, t2, t3, wq_dw, wk_dw, wv_dw,
                                           q, k, v, sqq, sqk);
    // 3) Gram (HMMA, 2 CTAs/SM, 72 chunks) + softmax (norms in-block)
    gram_mma<<<dim3(NCH2, BNH), 256, GR_SMEM>>>(q, k, part);
    attn_softmax<<<BNH, 256>>>(part, sqq, sqk, scale, out + BB*CC, a);
    // 4) fused a@v + LN -> t
    avln_kernel<<<avGrid, 256, AV_SMEM>>>(a, v, ln_o_w, ln_o_b, t);
    // 5) fused f1+f2 pointwise (GELU out) -> t2, t3
    f1f2<<<gGrid, 256, MM_SMEM>>>(whi, wlo, OF1, OF2, 0, t, nullptr, SB,
                                  nullptr, nullptr, t2, t3, nullptr, SB, nullptr, nullptr);
    // 6) depthwise FFN branches in ONE launch -> gelu'd split bf16 planes in g_q / g_k
    dwm_kernel<0, true><<<dwGrid2, 256>>>(t2, t3, nullptr, f1_dw, f2_dw, nullptr,
                                          q, k, nullptr, nullptr, nullptr);
    // 7) f_out (pre-split X, K=256) -> pool partials only
    fout<<<gGrid, 256, MM_SMEM>>>(whi, wlo, OFO, 0, 0, q, k, SB,
                                  nullptr, nullptr, nullptr, nullptr, nullptr, SB, psum, pmax);
    // 8) ChannelGate
    gate_pool_kernel<<<1, 128>>>(psum, pmax, g_w1, g_b1, g_w2, g_b2, out);
}

// round 15
// speedup vs baseline: 1.0263x; 1.0263x over previous
#include <cuda_runtime.h>
#include <cuda_bf16.h>
#include <math.h>
#include <stdint.h>

// ---------------- problem constants ----------------
#define BB 4
#define CC 128
#define HIMG 192
#define WIMG 192
#define PP (HIMG*WIMG)          // 36864
#define NH 2
#define HD 64
#define BNH (BB*NH)             // 8
#define NBX (PP/128)            // 288
#define NDW 9                   // dw blocks per plane (16 px/thread)
#define NCH2 32                 // gram chunks per (b,head)
#define CPX2 (PP/NCH2)          // 1152

#define ELEMS ((size_t)BB*CC*PP)

// weight-split offsets (elements)
#define OWQ 0
#define OWK 16384
#define OWV 32768
#define OF1 49152
#define OF2 65536
#define OFO 81920
#define WTOT 114688

// ---------------- scratch ----------------
__device__ float g_t [ELEMS];
__device__ float g_t2[ELEMS];
__device__ float g_t3[ELEMS];
__device__ float g_q [ELEMS];
__device__ float g_k [ELEMS];
__device__ float g_v [ELEMS];
__device__ float g_part[(size_t)BNH*NCH2*HD*HD];
__device__ float g_a[BNH*HD*HD];
__device__ float g_sqq[BB*CC*NDW];
__device__ float g_sqk[BB*CC*NDW];
__device__ float g_psum[BB*CC*NBX];
__device__ float g_pmax[BB*CC*NBX];
__device__ unsigned short g_whi[WTOT];
__device__ unsigned short g_wlo[WTOT];

__device__ __forceinline__ float gelu_f(float x) {
    return 0.5f * x * (1.0f + erff(x * 0.70710678118654752f));
}

// ================= mma.sync helpers =================
__device__ __forceinline__ uint32_t smem_u32(const void* p) {
    uint32_t a;
    asm("{ .reg .u64 t; cvta.to.shared.u64 t, %1; cvt.u32.u64 %0, t; }" : "=r"(a) : "l"(p));
    return a;
}
__device__ __forceinline__ void ldsm_x4(uint32_t* r, uint32_t addr) {
    asm volatile("ldmatrix.sync.aligned.m8n8.x4.shared.b16 {%0,%1,%2,%3}, [%4];"
        : "=r"(r[0]), "=r"(r[1]), "=r"(r[2]), "=r"(r[3]) : "r"(addr));
}
__device__ __forceinline__ void ldsm_x4_t(uint32_t* r, uint32_t addr) {
    asm volatile("ldmatrix.sync.aligned.m8n8.x4.trans.shared.b16 {%0,%1,%2,%3}, [%4];"
        : "=r"(r[0]), "=r"(r[1]), "=r"(r[2]), "=r"(r[3]) : "r"(addr));
}
__device__ __forceinline__ void mma_bf16(float* c, const uint32_t* a, uint32_t b0, uint32_t b1) {
    asm volatile(
        "mma.sync.aligned.m16n8k16.row.col.f32.bf16.bf16.f32 "
        "{%0,%1,%2,%3}, {%4,%5,%6,%7}, {%8,%9}, {%0,%1,%2,%3};"
        : "+f"(c[0]), "+f"(c[1]), "+f"(c[2]), "+f"(c[3])
        : "r"(a[0]), "r"(a[1]), "r"(a[2]), "r"(a[3]), "r"(b0), "r"(b1));
}
__device__ __forceinline__ void split2(float x, float y, uint32_t& hi, uint32_t& lo) {
    __nv_bfloat16 hx = __float2bfloat16_rn(x);
    __nv_bfloat16 hy = __float2bfloat16_rn(y);
    __nv_bfloat16 lx = __float2bfloat16_rn(x - __bfloat162float(hx));
    __nv_bfloat16 ly = __float2bfloat16_rn(y - __bfloat162float(hy));
    hi = (uint32_t)__bfloat16_as_ushort(hx) | ((uint32_t)__bfloat16_as_ushort(hy) << 16);
    lo = (uint32_t)__bfloat16_as_ushort(lx) | ((uint32_t)__bfloat16_as_ushort(ly) << 16);
}

// ---------------- merged weight split precompute (one launch) ----------------
__global__ void wprep_all(const float* __restrict__ wq, const float* __restrict__ wk,
                          const float* __restrict__ wv, const float* __restrict__ f1,
                          const float* __restrict__ f2, const float* __restrict__ fo,
                          unsigned short* __restrict__ hi, unsigned short* __restrict__ lo) {
    int i = blockIdx.x * 256 + threadIdx.x;
    if (i >= WTOT) return;
    const float* src; int off;
    if (i < OWK)      { src = wq; off = OWQ; }
    else if (i < OWV) { src = wk; off = OWK; }
    else if (i < OF1) { src = wv; off = OWV; }
    else if (i < OF2) { src = f1; off = OF1; }
    else if (i < OFO) { src = f2; off = OF2; }
    else              { src = fo; off = OFO; }
    float x = src[i - off];
    __nv_bfloat16 h = __float2bfloat16_rn(x);
    __nv_bfloat16 l = __float2bfloat16_rn(x - __bfloat162float(h));
    hi[i] = __bfloat16_as_ushort(h);
    lo[i] = __bfloat16_as_ushort(l);
}

// ============== fused HMMA pointwise GEMM (split-M: 64x128 tile, 2 CTAs/SM) ==============
#define LDA 136
#define XT_BYTES (128*LDA*2)
#define WT_BYTES (64*LDA*2)
#define MM_SMEM  (2*XT_BYTES + 2*WT_BYTES)     // 104448
#define MM_SMEM_LN (MM_SMEM + (2048 + 256)*4)  // 113664

template<int KPASS, int NSET, bool LNIN, bool PRESPLIT, bool GOUT, bool POOL, bool STORE>
__global__ void __launch_bounds__(256, 2) gemm_fused(
    const unsigned short* __restrict__ WHI, const unsigned short* __restrict__ WLO,
    long wo0, long wo1, long wo2,
    const void* __restrict__ X0, const void* __restrict__ X1, long xstride,
    const float* __restrict__ lnw, const float* __restrict__ lnb,
    float* __restrict__ Y0, float* __restrict__ Y1, float* __restrict__ Y2, long ystride,
    float* __restrict__ psum, float* __restrict__ pmax)
{
    extern __shared__ __align__(16) char smem[];
    uint32_t sX_hi = smem_u32(smem);
    uint32_t sX_lo = sX_hi + XT_BYTES;
    uint32_t sW_hi = sX_lo + XT_BYTES;
    uint32_t sW_lo = sW_hi + WT_BYTES;
    float* statsS = (float*)(smem + MM_SMEM);
    float* statsQ = statsS + 1024;
    float* muS    = statsQ + 1024;
    float* rsS    = muS + 128;

    const int tid = threadIdx.x;
    const int wid = tid >> 5, lane = tid & 31;
    const int bi = blockIdx.z;
    const int mh = blockIdx.y;
    const int p0 = blockIdx.x * 128;

    const int wm = wid & 1, wn = wid >> 1;
    const int m0 = wm * 32, n0 = wn * 32;
    const int ar = (lane & 7) + ((lane >> 3) & 1) * 8;
    const int ac = ((lane >> 4) & 1) * 8;
    const uint32_t offW = (uint32_t)((m0 + ar) * LDA + ac) * 2;
    const uint32_t offX = (uint32_t)(ar * LDA + n0 + ac) * 2;

    float C[2][4][4];
    if (KPASS > 1) {
        #pragma unroll
        for (int mt = 0; mt < 2; mt++)
            #pragma unroll
            for (int nt = 0; nt < 4; nt++)
                #pragma unroll
                for (int e = 0; e < 4; e++) C[mt][nt][e] = 0.f;
    }

    const int WROW = 128 * KPASS;

    #pragma unroll
    for (int pass = 0; pass < KPASS; pass++) {
        if (pass > 0) __syncthreads();

        if (PRESPLIT) {
            const unsigned short* Xh =
                (const unsigned short*)((pass == 0) ? X0 : X1) + (long)bi * xstride;
            const unsigned short* Xl = Xh + ELEMS;
            #pragma unroll
            for (int it = 0; it < 16; it++) {
                int idx = (it * 256 + tid) * 4;
                int kk = idx >> 7, nn = idx & 127;
                long src = (long)kk * PP + p0 + nn;
                uint2 h = *(const uint2*)&Xh[src];
                uint2 l = *(const uint2*)&Xl[src];
                uint32_t off = (uint32_t)(kk * LDA + nn) * 2;
                asm volatile("st.shared.v2.b32 [%0], {%1,%2};" :: "r"(sX_hi + off), "r"(h.x), "r"(h.y));
                asm volatile("st.shared.v2.b32 [%0], {%1,%2};" :: "r"(sX_lo + off), "r"(l.x), "r"(l.y));
            }
        } else {
            const float* Xsrc = (const float*)((pass == 0) ? X0 : X1) + (long)bi * xstride;
            if (LNIN) {
                float4 s4 = make_float4(0.f,0.f,0.f,0.f), q4 = make_float4(0.f,0.f,0.f,0.f);
                #pragma unroll
                for (int it = 0; it < 16; it++) {
                    int idx = (it * 256 + tid) * 4;
                    int kk = idx >> 7, nn = idx & 127;
                    float4 v = *(const float4*)&Xsrc[(long)kk * PP + p0 + nn];
                    s4.x += v.x; s4.y += v.y; s4.z += v.z; s4.w += v.w;
                    q4.x += v.x*v.x; q4.y += v.y*v.y; q4.z += v.z*v.z; q4.w += v.w*v.w;
                }
                {
                    int nn = (tid & 31) * 4;
                    *(float4*)&statsS[wid * 128 + nn] = s4;
                    *(float4*)&statsQ[wid * 128 + nn] = q4;
                }
                __syncthreads();
                if (tid < 128) {
                    float s = 0.f, q2 = 0.f;
                    #pragma unroll
                    for (int g = 0; g < 8; g++) { s += statsS[g * 128 + tid]; q2 += statsQ[g * 128 + tid]; }
                    float mu = s * (1.0f / 128.0f);
                    float var = q2 * (1.0f / 128.0f) - mu * mu;
                    muS[tid] = mu;
                    rsS[tid] = rsqrtf(var + 1e-5f);
                }
                __syncthreads();
                #pragma unroll
                for (int it = 0; it < 16; it++) {
                    int idx = (it * 256 + tid) * 4;
                    int kk = idx >> 7, nn = idx & 127;
                    float4 v = *(const float4*)&Xsrc[(long)kk * PP + p0 + nn];
                    float wc = __ldg(&lnw[kk]), bc = __ldg(&lnb[kk]);
                    v.x = (v.x - muS[nn + 0]) * rsS[nn + 0] * wc + bc;
                    v.y = (v.y - muS[nn + 1]) * rsS[nn + 1] * wc + bc;
                    v.z = (v.z - muS[nn + 2]) * rsS[nn + 2] * wc + bc;
                    v.w = (v.w - muS[nn + 3]) * rsS[nn + 3] * wc + bc;
                    uint32_t h0, l0, h1, l1;
                    split2(v.x, v.y, h0, l0);
                    split2(v.z, v.w, h1, l1);
                    uint32_t off = (uint32_t)(kk * LDA + nn) * 2;
                    asm volatile("st.shared.v2.b32 [%0], {%1,%2};" :: "r"(sX_hi + off), "r"(h0), "r"(h1));
                    asm volatile("st.shared.v2.b32 [%0], {%1,%2};" :: "r"(sX_lo + off), "r"(l0), "r"(l1));
                }
            } else {
                #pragma unroll
                for (int it = 0; it < 16; it++) {
                    int idx = (it * 256 + tid) * 4;
                    int kk = idx >> 7, nn = idx & 127;
                    float4 v = *(const float4*)&Xsrc[(long)kk * PP + p0 + nn];
                    uint32_t h0, l0, h1, l1;
                    split2(v.x, v.y, h0, l0);
                    split2(v.z, v.w, h1, l1);
                    uint32_t off = (uint32_t)(kk * LDA + nn) * 2;
                    asm volatile("st.shared.v2.b32 [%0], {%1,%2};" :: "r"(sX_hi + off), "r"(h0), "r"(h1));
                    asm volatile("st.shared.v2.b32 [%0], {%1,%2};" :: "r"(sX_lo + off), "r"(l0), "r"(l1));
                }
            }
        }

        #pragma unroll
        for (int s = 0; s < NSET; s++) {
            if (pass > 0 || s > 0) __syncthreads();
            const long wo = (s == 0) ? wo0 : ((s == 1) ? wo1 : wo2);
            #pragma unroll
            for (int it = 0; it < 8; it++) {
                int idx = (it * 256 + tid) * 4;
                int co = idx >> 7, k = idx & 127;
                long src = wo + (long)(mh * 64 + co) * WROW + pass * 128 + k;
                uint2 h = *(const uint2*)&WHI[src];
                uint2 l = *(const uint2*)&WLO[src];
                uint32_t off = (uint32_t)(co * LDA + k) * 2;
                asm volatile("st.shared.v2.b32 [%0], {%1,%2};" :: "r"(sW_hi + off), "r"(h.x), "r"(h.y));
                asm volatile("st.shared.v2.b32 [%0], {%1,%2};" :: "r"(sW_lo + off), "r"(l.x), "r"(l.y));
            }
            __syncthreads();

            if (KPASS == 1) {
                #pragma unroll
                for (int mt = 0; mt < 2; mt++)
                    #pragma unroll
                    for (int nt = 0; nt < 4; nt++)
                        #pragma unroll
                        for (int e = 0; e < 4; e++) C[mt][nt][e] = 0.f;
            }

            #pragma unroll
            for (int kk = 0; kk < 8; kk++) {
                int k0 = kk * 16;
                uint32_t ah[2][4], al[2][4];
                #pragma unroll
                for (int mt = 0; mt < 2; mt++) {
                    uint32_t o = offW + (uint32_t)(mt * 16 * LDA + k0) * 2;
                    ldsm_x4(ah[mt], sW_hi + o);
                    ldsm_x4(al[mt], sW_lo + o);
                }
                uint32_t bh[2][4], bl[2][4];
                #pragma unroll
                for (int bt = 0; bt < 2; bt++) {
                    uint32_t o = offX + (uint32_t)(k0 * LDA + bt * 16) * 2;
                    ldsm_x4_t(bh[bt], sX_hi + o);
                    ldsm_x4_t(bl[bt], sX_lo + o);
                }
                #pragma unroll
                for (int mt = 0; mt < 2; mt++)
                    #pragma unroll
                    for (int nt = 0; nt < 4; nt++) {
                        uint32_t b0h = bh[nt >> 1][(nt & 1) * 2], b1h = bh[nt >> 1][(nt & 1) * 2 + 1];
                        uint32_t b0l = bl[nt >> 1][(nt & 1) * 2], b1l = bl[nt >> 1][(nt & 1) * 2 + 1];
                        mma_bf16(C[mt][nt], ah[mt], b0h, b1h);
                        mma_bf16(C[mt][nt], ah[mt], b0l, b1l);
                        mma_bf16(C[mt][nt], al[mt], b0h, b1h);
                    }
            }

            if (KPASS == 1 && STORE) {
                float* Yb = ((s == 0) ? Y0 : ((s == 1) ? Y1 : Y2)) + (long)bi * ystride;
                const int g = lane >> 2, i2 = (lane & 3) * 2;
                #pragma unroll
                for (int mt = 0; mt < 2; mt++) {
                    int row0 = mh * 64 + m0 + mt * 16 + g;
                    #pragma unroll
                    for (int nt = 0; nt < 4; nt++) {
                        int p = p0 + n0 + nt * 8 + i2;
                        float2 o0 = make_float2(C[mt][nt][0], C[mt][nt][1]);
                        float2 o1 = make_float2(C[mt][nt][2], C[mt][nt][3]);
                        if (GOUT) {
                            o0.x = gelu_f(o0.x); o0.y = gelu_f(o0.y);
                            o1.x = gelu_f(o1.x); o1.y = gelu_f(o1.y);
                        }
                        *(float2*)&Yb[(long)row0 * PP + p]       = o0;
                        *(float2*)&Yb[(long)(row0 + 8) * PP + p] = o1;
                    }
                }
            }
        }
    }

    if (POOL) {
        __syncthreads();
        float* ps = (float*)smem;
        float* pm = ps + 256;
        const int g = lane >> 2;
        #pragma unroll
        for (int mt = 0; mt < 2; mt++) {
            float s0 = 0.f, s1 = 0.f, m0v = -INFINITY, m1v = -INFINITY;
            #pragma unroll
            for (int nt = 0; nt < 4; nt++) {
                s0 += C[mt][nt][0] + C[mt][nt][1];
                m0v = fmaxf(m0v, fmaxf(C[mt][nt][0], C[mt][nt][1]));
                s1 += C[mt][nt][2] + C[mt][nt][3];
                m1v = fmaxf(m1v, fmaxf(C[mt][nt][2], C[mt][nt][3]));
            }
            #pragma unroll
            for (int o = 1; o <= 2; o <<= 1) {
                s0 += __shfl_xor_sync(0xffffffffu, s0, o);
                s1 += __shfl_xor_sync(0xffffffffu, s1, o);
                m0v = fmaxf(m0v, __shfl_xor_sync(0xffffffffu, m0v, o));
                m1v = fmaxf(m1v, __shfl_xor_sync(0xffffffffu, m1v, o));
            }
            if ((lane & 3) == 0) {
                int r0 = m0 + mt * 16 + g;
                ps[r0 * 4 + wn] = s0;       pm[r0 * 4 + wn] = m0v;
                ps[(r0 + 8) * 4 + wn] = s1; pm[(r0 + 8) * 4 + wn] = m1v;
            }
        }
        __syncthreads();
        if (tid < 64) {
            float s = ps[tid*4] + ps[tid*4+1] + ps[tid*4+2] + ps[tid*4+3];
            float m = fmaxf(fmaxf(pm[tid*4], pm[tid*4+1]), fmaxf(pm[tid*4+2], pm[tid*4+3]));
            long ch = (long)(bi * CC + mh * 64 + tid);
            psum[ch * NBX + blockIdx.x] = s;
            pmax[ch * NBX + blockIdx.x] = m;
        }
    }
}

// ---------------- multi-tensor depthwise 3x3 pad 1: 4x4 px/thread ----------------
template<int SQMASK, bool GSPLIT>
__global__ void __launch_bounds__(256) dwm_kernel(
    const float* __restrict__ x0, const float* __restrict__ x1, const float* __restrict__ x2,
    const float* __restrict__ w0, const float* __restrict__ w1, const float* __restrict__ w2,
    void* __restrict__ y0, void* __restrict__ y1, void* __restrict__ y2,
    float* __restrict__ sq0, float* __restrict__ sq1) {
    int i = blockIdx.x * 256 + threadIdx.x;
    int bc = blockIdx.y;
    int z  = blockIdx.z;
    const float* x = (z == 0) ? x0 : ((z == 1) ? x1 : x2);
    const float* w = (z == 0) ? w0 : ((z == 1) ? w1 : w2);
    void* yout     = (z == 0) ? y0 : ((z == 1) ? y1 : y2);
    const bool doSQ = (SQMASK >> z) & 1;

    int rq = i / 48, cg = i % 48;
    int y0r = rq * 4, xx = cg * 4;
    const float* xp = x + (size_t)bc * PP;
    const float* wc = w + (bc % CC) * 9;
    float kw[3][3];
    #pragma unroll
    for (int j = 0; j < 9; j++) kw[j/3][j%3] = wc[j];

    float4 c[6]; float lf[6], rt[6];
    #pragma unroll
    for (int r = 0; r < 6; r++) {
        int sy = y0r - 1 + r;
        bool ok = (unsigned)sy < HIMG;
        const float* row = xp + sy * WIMG + xx;
        c[r]  = ok ? *(const float4*)row : make_float4(0.f, 0.f, 0.f, 0.f);
        lf[r] = (ok && xx > 0) ? row[-1] : 0.f;
        rt[r] = (ok && xx + 4 < WIMG) ? row[4] : 0.f;
    }

    float4 a[4];
    #pragma unroll
    for (int r = 0; r < 4; r++) a[r] = make_float4(0.f, 0.f, 0.f, 0.f);
    #pragma unroll
    for (int ky = 0; ky < 3; ky++) {
        float k0 = kw[ky][0], k1 = kw[ky][1], k2 = kw[ky][2];
        #pragma unroll
        for (int r = 0; r < 4; r++) {
            float4 cc = c[r + ky]; float l = lf[r + ky], rr = rt[r + ky];
            a[r].x += k0*l    + k1*cc.x + k2*cc.y;
            a[r].y += k0*cc.x + k1*cc.y + k2*cc.z;
            a[r].z += k0*cc.y + k1*cc.z + k2*cc.w;
            a[r].w += k0*cc.z + k1*cc.w + k2*rr;
        }
    }

    if (GSPLIT) {
        unsigned short* yh = (unsigned short*)yout;
        unsigned short* yl = yh + ELEMS;
        #pragma unroll
        for (int r = 0; r < 4; r++) {
            float gx = gelu_f(a[r].x), gy = gelu_f(a[r].y);
            float gz = gelu_f(a[r].z), gw = gelu_f(a[r].w);
            uint32_t h0, l0, h1, l1;
            split2(gx, gy, h0, l0);
            split2(gz, gw, h1, l1);
            size_t o = (size_t)bc * PP + (y0r + r) * WIMG + xx;
            *(uint2*)&yh[o] = make_uint2(h0, h1);
            *(uint2*)&yl[o] = make_uint2(l0, l1);
        }
    } else {
        float* yp = (float*)yout + (size_t)bc * PP;
        #pragma unroll
        for (int r = 0; r < 4; r++)
            *(float4*)&yp[(y0r + r) * WIMG + xx] = a[r];
    }

    if (SQMASK) {
        if (doSQ) {
            float s = 0.f;
            #pragma unroll
            for (int r = 0; r < 4; r++)
                s += a[r].x*a[r].x + a[r].y*a[r].y + a[r].z*a[r].z + a[r].w*a[r].w;
            __shared__ float red[256];
            red[threadIdx.x] = s; __syncthreads();
            for (int o = 128; o > 0; o >>= 1) {
                if (threadIdx.x < o) red[threadIdx.x] += red[threadIdx.x + o];
                __syncthreads();
            }
            if (threadIdx.x == 0) {
                float* sqp = (z == 0) ? sq0 : sq1;
                sqp[bc * NDW + blockIdx.x] = red[0];
            }
        }
    }
}

// ---------------- Gram partials via HMMA (bf16 split, 2 CTAs/SM) ----------------
#define LDK 136
#define GT_BYTES (64*LDK*2)
#define GR_SMEM (4*GT_BYTES)
__global__ void __launch_bounds__(256, 2) gram_mma(const float* __restrict__ q,
                                                   const float* __restrict__ k,
                                                   float* __restrict__ part) {
    extern __shared__ __align__(16) char smem[];
    uint32_t sb = smem_u32(smem);
    uint32_t sQ_hi = sb, sQ_lo = sb + GT_BYTES;
    uint32_t sK_hi = sb + 2*GT_BYTES, sK_lo = sb + 3*GT_BYTES;

    const int tid = threadIdx.x;
    const int wid = tid >> 5, lane = tid & 31;
    const int ch = blockIdx.x, bn = blockIdx.y;
    const float* qb = q + (size_t)bn * HD * PP + ch * CPX2;
    const float* kb = k + (size_t)bn * HD * PP + ch * CPX2;

    const int wm = wid & 1, wn = wid >> 1;
    const int m0 = wm * 32, n0 = wn * 16;
    const int ar = (lane & 7) + ((lane >> 3) & 1) * 8;
    const int ac = ((lane >> 4) & 1) * 8;
    const uint32_t offA = (uint32_t)((m0 + ar) * LDK + ac) * 2;
    const uint32_t offB = (uint32_t)((n0 + ar) * LDK + ac) * 2;

    float C[2][2][4];
    #pragma unroll
    for (int mt = 0; mt < 2; mt++)
        #pragma unroll
        for (int nt = 0; nt < 2; nt++)
            #pragma unroll
            for (int e = 0; e < 4; e++) C[mt][nt][e] = 0.f;

    for (int t = 0; t < CPX2 / 128; t++) {
        if (t > 0) __syncthreads();
        #pragma unroll
        for (int it = 0; it < 8; it++) {
            int idx = (it * 256 + tid) * 4;
            int r = idx >> 7, n = idx & 127;
            float4 v = *(const float4*)&qb[(size_t)r * PP + t * 128 + n];
            uint32_t h0, l0, h1, l1;
            split2(v.x, v.y, h0, l0); split2(v.z, v.w, h1, l1);
            uint32_t off = (uint32_t)(r * LDK + n) * 2;
            asm volatile("st.shared.v2.b32 [%0], {%1,%2};" :: "r"(sQ_hi + off), "r"(h0), "r"(h1));
            asm volatile("st.shared.v2.b32 [%0], {%1,%2};" :: "r"(sQ_lo + off), "r"(l0), "r"(l1));
        }
        #pragma unroll
        for (int it = 0; it < 8; it++) {
            int idx = (it * 256 + tid) * 4;
            int r = idx >> 7, n = idx & 127;
            float4 v = *(const float4*)&kb[(size_t)r * PP + t * 128 + n];
            uint32_t h0, l0, h1, l1;
            split2(v.x, v.y, h0, l0); split2(v.z, v.w, h1, l1);
            uint32_t off = (uint32_t)(r * LDK + n) * 2;
            asm volatile("st.shared.v2.b32 [%0], {%1,%2};" :: "r"(sK_hi + off), "r"(h0), "r"(h1));
            asm volatile("st.shared.v2.b32 [%0], {%1,%2};" :: "r"(sK_lo + off), "r"(l0), "r"(l1));
        }
        __syncthreads();

        #pragma unroll
        for (int kk = 0; kk < 8; kk++) {
            int k0 = kk * 16;
            uint32_t ah[2][4], al[2][4];
            #pragma unroll
            for (int mt = 0; mt < 2; mt++) {
                uint32_t o = offA + (uint32_t)(mt * 16 * LDK + k0) * 2;
                ldsm_x4(ah[mt], sQ_hi + o);
                ldsm_x4(al[mt], sQ_lo + o);
            }
            uint32_t bh[4], bl[4];
            ldsm_x4(bh, sK_hi + offB + (uint32_t)k0 * 2);
            ldsm_x4(bl, sK_lo + offB + (uint32_t)k0 * 2);
            #pragma unroll
            for (int mt = 0; mt < 2; mt++) {
                mma_bf16(C[mt][0], ah[mt], bh[0], bh[2]);
                mma_bf16(C[mt][1], ah[mt], bh[1], bh[3]);
                mma_bf16(C[mt][0], ah[mt], bl[0], bl[2]);
                mma_bf16(C[mt][1], ah[mt], bl[1], bl[3]);
                mma_bf16(C[mt][0], al[mt], bh[0], bh[2]);
                mma_bf16(C[mt][1], al[mt], bh[1], bh[3]);
            }
        }
    }

    float* pb = part + (((size_t)bn * NCH2 + ch) * HD) * HD;
    const int g = lane >> 2, i2 = (lane & 3) * 2;
    #pragma unroll
    for (int mt = 0; mt < 2; mt++) {
        int i = m0 + mt * 16 + g;
        #pragma unroll
        for (int nt = 0; nt < 2; nt++) {
            int j = n0 + nt * 8 + i2;
            pb[i * HD + j]       = C[mt][nt][0];
            pb[i * HD + j + 1]   = C[mt][nt][1];
            pb[(i + 8) * HD + j]     = C[mt][nt][2];
            pb[(i + 8) * HD + j + 1] = C[mt][nt][3];
        }
    }
}

// ---------------- norms (from dw sumsq partials) + reduce + softmax ----------------
__global__ void attn_softmax(const float* __restrict__ part,
                             const float* __restrict__ sqq, const float* __restrict__ sqk,
                             const float* __restrict__ scale,
                             float* __restrict__ attnw_out, float* __restrict__ a) {
    __shared__ float nqS[HD], nkS[HD];
    int bn = blockIdx.x;
    int n = bn % NH;
    int tid = threadIdx.x;
    int warp = tid / 32, lane = tid % 32;

    if (tid < 128) {
        int i = tid & 63;
        const float* sp = (tid < 64) ? sqq : sqk;
        float s = 0.f;
        #pragma unroll
        for (int j = 0; j < NDW; j++) s += sp[(bn * HD + i) * NDW + j];
        float nv = fmaxf(sqrtf(s), 1e-12f);
        if (tid < 64) nqS[i] = nv; else nkS[i] = nv;
    }
    __syncthreads();

    float sc = scale[n];
    for (int i = warp; i < HD; i += 8) {
        float v[2];
        #pragma unroll
        for (int h = 0; h < 2; h++) {
            int j = lane + 32 * h;
            float s = 0.f;
            for (int ch = 0; ch < NCH2; ch++)
                s += part[(((size_t)bn * NCH2 + ch) * HD + i) * HD + j];
            s = s * sc / (nqS[i] * nkS[j]);
            attnw_out[((size_t)bn * HD + i) * HD + j] = s;
            v[h] = s;
        }
        float m = fmaxf(v[0], v[1]);
        #pragma unroll
        for (int o = 16; o; o >>= 1) m = fmaxf(m, __shfl_xor_sync(0xffffffffu, m, o));
        float e0 = expf(v[0] - m), e1 = expf(v[1] - m);
        float s = e0 + e1;
        #pragma unroll
        for (int o = 16; o; o >>= 1) s += __shfl_xor_sync(0xffffffffu, s, o);
        float inv = 1.0f / s;
        a[((size_t)bn * HD + i) * HD + lane]      = e0 * inv;
        a[((size_t)bn * HD + i) * HD + lane + 32] = e1 * inv;
    }
}

// ---------------- fused a@v + channel-LN ----------------
#define AV_SMEM (8192*4 + 128*132*4 + (2*1024 + 256)*4)
__global__ void __launch_bounds__(256) avln_kernel(
    const float* __restrict__ a, const float* __restrict__ v,
    const float* __restrict__ lnw, const float* __restrict__ lnb,
    float* __restrict__ t)
{
    extern __shared__ __align__(16) float dsm[];
    float* As = dsm;
    float* Vs = As + 8192;
    float* redS = Vs + 128*132;
    float* redQ = redS + 1024;
    float* muA  = redQ + 1024;
    float* rsA  = muA + 128;

    const int tid = threadIdx.x;
    const int bi = blockIdx.y;
    const int p0 = blockIdx.x * 128;

    const float* ab = a + (size_t)bi * 2 * 4096;
    #pragma unroll
    for (int it = 0; it < 8; it++) {
        int idx = (it * 256 + tid) * 4;
        *(float4*)&As[idx] = *(const float4*)&ab[idx];
    }
    const float* vb = v + (size_t)bi * CC * PP;
    #pragma unroll
    for (int it = 0; it < 16; it++) {
        int idx = it * 256 + tid;
        int row = idx >> 5, n4 = idx & 31;
        *(float4*)&Vs[row * 132 + n4 * 4] = *(const float4*)&vb[(size_t)row * PP + p0 + n4 * 4];
    }
    __syncthreads();

    const int px4 = tid & 31;
    const int cg = tid >> 5;
    const int h = cg >> 2;
    const int cbase = cg * 16;
    const float* Ah = As + h * 4096;

    float4 acc[16];
    #pragma unroll
    for (int cl = 0; cl < 16; cl++) acc[cl] = make_float4(0.f, 0.f, 0.f, 0.f);

    #pragma unroll
    for (int j4 = 0; j4 < 16; j4++) {
        float4 vv0 = *(float4*)&Vs[(h*64 + j4*4 + 0) * 132 + px4*4];
        float4 vv1 = *(float4*)&Vs[(h*64 + j4*4 + 1) * 132 + px4*4];
        float4 vv2 = *(float4*)&Vs[(h*64 + j4*4 + 2) * 132 + px4*4];
        float4 vv3 = *(float4*)&Vs[(h*64 + j4*4 + 3) * 132 + px4*4];
        #pragma unroll
        for (int cl = 0; cl < 16; cl++) {
            int i = (cbase + cl) & 63;
            float4 a4 = *(float4*)&Ah[i * 64 + j4 * 4];
            acc[cl].x += a4.x*vv0.x + a4.y*vv1.x + a4.z*vv2.x + a4.w*vv3.x;
            acc[cl].y += a4.x*vv0.y + a4.y*vv1.y + a4.z*vv2.y + a4.w*vv3.y;
            acc[cl].z += a4.x*vv0.z + a4.y*vv1.z + a4.z*vv2.z + a4.w*vv3.z;
            acc[cl].w += a4.x*vv0.w + a4.y*vv1.w + a4.z*vv2.w + a4.w*vv3.w;
        }
    }

    float4 s4 = make_float4(0.f,0.f,0.f,0.f), q4 = make_float4(0.f,0.f,0.f,0.f);
    #pragma unroll
    for (int cl = 0; cl < 16; cl++) {
        s4.x += acc[cl].x; s4.y += acc[cl].y; s4.z += acc[cl].z; s4.w += acc[cl].w;
        q4.x += acc[cl].x*acc[cl].x; q4.y += acc[cl].y*acc[cl].y;
        q4.z += acc[cl].z*acc[cl].z; q4.w += acc[cl].w*acc[cl].w;
    }
    *(float4*)&redS[cg * 128 + px4 * 4] = s4;
    *(float4*)&redQ[cg * 128 + px4 * 4] = q4;
    __syncthreads();
    if (tid < 128) {
        float s = 0.f, q2 = 0.f;
        #pragma unroll
        for (int g = 0; g < 8; g++) { s += redS[g * 128 + tid]; q2 += redQ[g * 128 + tid]; }
        float mu = s * (1.0f / 128.0f);
        float var = q2 * (1.0f / 128.0f) - mu * mu;
        muA[tid] = mu;
        rsA[tid] = rsqrtf(var + 1e-5f);
    }
    __syncthreads();

    float4 mu4 = *(float4*)&muA[px4 * 4];
    float4 rs4 = *(float4*)&rsA[px4 * 4];
    float* tb = t + (size_t)bi * CC * PP;
    #pragma unroll
    for (int cl = 0; cl < 16; cl++) {
        int c = cbase + cl;
        float w = __ldg(&lnw[c]), b = __ldg(&lnb[c]);
        float4 o;
        o.x = (acc[cl].x - mu4.x) * rs4.x * w + b;
        o.y = (acc[cl].y - mu4.y) * rs4.y * w + b;
        o.z = (acc[cl].z - mu4.z) * rs4.z * w + b;
        o.w = (acc[cl].w - mu4.w) * rs4.w * w + b;
        *(float4*)&tb[(size_t)c * PP + p0 + px4 * 4] = o;
    }
}

// ---------------- pool partial reduce + ChannelGate ----------------
__global__ void gate_pool_kernel(const float* __restrict__ psum, const float* __restrict__ pmax,
                                 const float* __restrict__ w1, const float* __restrict__ b1,
                                 const float* __restrict__ w2, const float* __restrict__ b2,
                                 float* __restrict__ out) {
    __shared__ float sa[CC], sm_[CC], ha[8], hm[8];
    int c = threadIdx.x;
    for (int b = 0; b < BB; b++) {
        float s = 0.f, m = -INFINITY;
        long base = (long)(b * CC + c) * NBX;
        for (int i = 0; i < NBX; i++) {
            s += psum[base + i];
            m = fmaxf(m, pmax[base + i]);
        }
        sa[c] = s * (1.0f / PP);
        sm_[c] = m;
        __syncthreads();
        if (c < 8) {
            float xa = b1[c], xm = b1[c];
            for (int cc = 0; cc < CC; cc++) {
                xa += w1[c*CC + cc] * sa[cc];
                xm += w1[c*CC + cc] * sm_[cc];
            }
            ha[c] = fmaxf(xa, 0.f);
            hm[c] = fmaxf(xm, 0.f);
        }
        __syncthreads();
        float xa = b2[c], xm = b2[c];
        #pragma unroll
        for (int j = 0; j < 8; j++) {
            xa += w2[c*8 + j] * ha[j];
            xm += w2[c*8 + j] * hm[j];
        }
        out[b*CC + c] = 1.0f / (1.0f + expf(-(xa + xm)));
        __syncthreads();
    }
}

// ---------------- host launch ----------------
static float* sym(const void* s) {
    void* p = nullptr;
    cudaGetSymbolAddress(&p, s);
    return (float*)p;
}

extern "C" void kernel_launch(void* const* d_in, const int* in_sizes, int n_in,
                              void* d_out, int out_size) {
    const float* x       = (const float*)d_in[0];
    const float* ln_in_w = (const float*)d_in[1];
    const float* ln_in_b = (const float*)d_in[2];
    const float* wq_pw   = (const float*)d_in[3];
    const float* wq_dw   = (const float*)d_in[4];
    const float* wk_pw   = (const float*)d_in[5];
    const float* wk_dw   = (const float*)d_in[6];
    const float* wv_pw   = (const float*)d_in[7];
    const float* wv_dw   = (const float*)d_in[8];
    const float* scale   = (const float*)d_in[9];
    const float* ln_o_w  = (const float*)d_in[10];
    const float* ln_o_b  = (const float*)d_in[11];
    const float* f1_pw   = (const float*)d_in[12];
    const float* f1_dw   = (const float*)d_in[13];
    const float* f2_pw   = (const float*)d_in[14];
    const float* f2_dw   = (const float*)d_in[15];
    const float* f_out   = (const float*)d_in[16];
    const float* g_w1    = (const float*)d_in[17];
    const float* g_b1    = (const float*)d_in[18];
    const float* g_w2    = (const float*)d_in[19];
    const float* g_b2    = (const float*)d_in[20];
    float* out = (float*)d_out;

    float* t  = sym(g_t);   float* t2 = sym(g_t2);  float* t3 = sym(g_t3);
    float* q  = sym(g_q);   float* k  = sym(g_k);   float* v  = sym(g_v);
    float* part = sym(g_part); float* a = sym(g_a);
    float* sqq = sym(g_sqq);   float* sqk = sym(g_sqk);
    float* psum = sym(g_psum); float* pmax = sym(g_pmax);
    unsigned short* whi = (unsigned short*)sym(g_whi);
    unsigned short* wlo = (unsigned short*)sym(g_wlo);

    auto qkv  = gemm_fused<1,3,true, false,false,false,true>;
    auto f1f2 = gemm_fused<1,2,false,false,true, false,true>;
    auto fout = gemm_fused<2,1,false,true, false,true, false>;
    cudaFuncSetAttribute(qkv,  cudaFuncAttributeMaxDynamicSharedMemorySize, MM_SMEM_LN);
    cudaFuncSetAttribute(f1f2, cudaFuncAttributeMaxDynamicSharedMemorySize, MM_SMEM);
    cudaFuncSetAttribute(fout, cudaFuncAttributeMaxDynamicSharedMemorySize, MM_SMEM);
    cudaFuncSetAttribute(gram_mma, cudaFuncAttributeMaxDynamicSharedMemorySize, GR_SMEM);
    cudaFuncSetAttribute(avln_kernel, cudaFuncAttributeMaxDynamicSharedMemorySize, AV_SMEM);

    const long SB = (long)CC * PP;
    dim3 gGrid(NBX, 2, BB);
    dim3 dwGrid3(NDW, BB*CC, 3);
    dim3 dwGrid2(NDW, BB*CC, 2);
    dim3 avGrid(NBX, BB);

    // 0) precompute weight hi/lo splits (single merged launch)
    wprep_all<<<(WTOT + 255)/256, 256>>>(wq_pw, wk_pw, wv_pw, f1_pw, f2_pw, f_out, whi, wlo);

    // 1) fused LN + QKV pointwise
    qkv<<<gGrid, 256, MM_SMEM_LN>>>(whi, wlo, OWQ, OWK, OWV, x, nullptr, SB,
                                    ln_in_w, ln_in_b, t, t2, t3, SB, nullptr, nullptr);
    // 2) depthwise q/k/v in ONE launch (+ sumsq partials for q,k)
    dwm_kernel<3, false><<<dwGrid3, 256>>>(t, t2, t3, wq_dw, wk_dw, wv_dw,
                                           q, k, v, sqq, sqk);
    // 3) Gram (HMMA, 2 CTAs/SM) + softmax (norms in-block; attn_weight -> d_out + 512)
    gram_mma<<<dim3(NCH2, BNH), 256, GR_SMEM>>>(q, k, part);
    attn_softmax<<<BNH, 256>>>(part, sqq, sqk, scale, out + BB*CC, a);
    // 4) fused a@v + LN -> t
    avln_kernel<<<avGrid, 256, AV_SMEM>>>(a, v, ln_o_w, ln_o_b, t);
    // 5) fused f1+f2 pointwise (GELU out) -> t2, t3
    f1f2<<<gGrid, 256, MM_SMEM>>>(whi, wlo, OF1, OF2, 0, t, nullptr, SB,
                                  nullptr, nullptr, t2, t3, nullptr, SB, nullptr, nullptr);
    // 6) depthwise FFN branches in ONE launch -> gelu'd split bf16 planes in g_q / g_k
    dwm_kernel<0, true><<<dwGrid2, 256>>>(t2, t3, nullptr, f1_dw, f2_dw, nullptr,
                                          q, k, nullptr, nullptr, nullptr);
    // 7) f_out (pre-split X, K=256) -> pool partials only
    fout<<<gGrid, 256, MM_SMEM>>>(whi, wlo, OFO, 0, 0, q, k, SB,
                                  nullptr, nullptr, nullptr, nullptr, nullptr, SB, psum, pmax);
    // 8) ChannelGate
    gate_pool_kernel<<<1, 128>>>(psum, pmax, g_w1, g_b1, g_w2, g_b2, out);
}

// round 16
// speedup vs baseline: 1.0273x; 1.0009x over previous
#include <cuda_runtime.h>
#include <cuda_bf16.h>
#include <math.h>
#include <stdint.h>

// ---------------- problem constants ----------------
#define BB 4
#define CC 128
#define HIMG 192
#define WIMG 192
#define PP (HIMG*WIMG)          // 36864
#define NH 2
#define HD 64
#define BNH (BB*NH)             // 8
#define NBX (PP/128)            // 288
#define NDW 9                   // dw blocks per plane (16 px/thread)
#define NCH2 32                 // gram chunks per (b,head)
#define CPX2 (PP/NCH2)          // 1152

#define ELEMS ((size_t)BB*CC*PP)

// weight-split offsets (elements)
#define OWQ 0
#define OWK 16384
#define OWV 32768
#define OF1 49152
#define OF2 65536
#define OFO 81920
#define WTOT 114688

// ---------------- scratch ----------------
__device__ float g_t [ELEMS];
__device__ float g_t2[ELEMS];
__device__ float g_t3[ELEMS];
__device__ float g_q [ELEMS];   // ushort hi/lo planes (attention q, FFN o1)
__device__ float g_k [ELEMS];   // ushort hi/lo planes (attention k, FFN o2)
__device__ float g_v [ELEMS];
__device__ float g_part[(size_t)BNH*NCH2*HD*HD];
__device__ float g_a[BNH*HD*HD];
__device__ float g_sqq[BB*CC*NDW];
__device__ float g_sqk[BB*CC*NDW];
__device__ float g_psum[BB*CC*NBX];
__device__ float g_pmax[BB*CC*NBX];
__device__ unsigned short g_whi[WTOT];
__device__ unsigned short g_wlo[WTOT];

__device__ __forceinline__ float gelu_f(float x) {
    return 0.5f * x * (1.0f + erff(x * 0.70710678118654752f));
}

// ================= mma.sync helpers =================
__device__ __forceinline__ uint32_t smem_u32(const void* p) {
    uint32_t a;
    asm("{ .reg .u64 t; cvta.to.shared.u64 t, %1; cvt.u32.u64 %0, t; }" : "=r"(a) : "l"(p));
    return a;
}
__device__ __forceinline__ void ldsm_x4(uint32_t* r, uint32_t addr) {
    asm volatile("ldmatrix.sync.aligned.m8n8.x4.shared.b16 {%0,%1,%2,%3}, [%4];"
        : "=r"(r[0]), "=r"(r[1]), "=r"(r[2]), "=r"(r[3]) : "r"(addr));
}
__device__ __forceinline__ void ldsm_x4_t(uint32_t* r, uint32_t addr) {
    asm volatile("ldmatrix.sync.aligned.m8n8.x4.trans.shared.b16 {%0,%1,%2,%3}, [%4];"
        : "=r"(r[0]), "=r"(r[1]), "=r"(r[2]), "=r"(r[3]) : "r"(addr));
}
__device__ __forceinline__ void mma_bf16(float* c, const uint32_t* a, uint32_t b0, uint32_t b1) {
    asm volatile(
        "mma.sync.aligned.m16n8k16.row.col.f32.bf16.bf16.f32 "
        "{%0,%1,%2,%3}, {%4,%5,%6,%7}, {%8,%9}, {%0,%1,%2,%3};"
        : "+f"(c[0]), "+f"(c[1]), "+f"(c[2]), "+f"(c[3])
        : "r"(a[0]), "r"(a[1]), "r"(a[2]), "r"(a[3]), "r"(b0), "r"(b1));
}
__device__ __forceinline__ void split2(float x, float y, uint32_t& hi, uint32_t& lo) {
    __nv_bfloat16 hx = __float2bfloat16_rn(x);
    __nv_bfloat16 hy = __float2bfloat16_rn(y);
    __nv_bfloat16 lx = __float2bfloat16_rn(x - __bfloat162float(hx));
    __nv_bfloat16 ly = __float2bfloat16_rn(y - __bfloat162float(hy));
    hi = (uint32_t)__bfloat16_as_ushort(hx) | ((uint32_t)__bfloat16_as_ushort(hy) << 16);
    lo = (uint32_t)__bfloat16_as_ushort(lx) | ((uint32_t)__bfloat16_as_ushort(ly) << 16);
}

// ---------------- merged weight split precompute (one launch) ----------------
__global__ void wprep_all(const float* __restrict__ wq, const float* __restrict__ wk,
                          const float* __restrict__ wv, const float* __restrict__ f1,
                          const float* __restrict__ f2, const float* __restrict__ fo,
                          unsigned short* __restrict__ hi, unsigned short* __restrict__ lo) {
    int i = blockIdx.x * 256 + threadIdx.x;
    if (i >= WTOT) return;
    const float* src; int off;
    if (i < OWK)      { src = wq; off = OWQ; }
    else if (i < OWV) { src = wk; off = OWK; }
    else if (i < OF1) { src = wv; off = OWV; }
    else if (i < OF2) { src = f1; off = OF1; }
    else if (i < OFO) { src = f2; off = OF2; }
    else              { src = fo; off = OFO; }
    float x = src[i - off];
    __nv_bfloat16 h = __float2bfloat16_rn(x);
    __nv_bfloat16 l = __float2bfloat16_rn(x - __bfloat162float(h));
    hi[i] = __bfloat16_as_ushort(h);
    lo[i] = __bfloat16_as_ushort(l);
}

// ============== fused HMMA pointwise GEMM (split-M: 64x128 tile, 2 CTAs/SM) ==============
#define LDA 136
#define XT_BYTES (128*LDA*2)
#define WT_BYTES (64*LDA*2)
#define MM_SMEM  (2*XT_BYTES + 2*WT_BYTES)     // 104448
#define MM_SMEM_LN (MM_SMEM + (2048 + 256)*4)  // 113664

template<int KPASS, int NSET, bool LNIN, bool PRESPLIT, bool GOUT, bool POOL, bool STORE>
__global__ void __launch_bounds__(256, 2) gemm_fused(
    const unsigned short* __restrict__ WHI, const unsigned short* __restrict__ WLO,
    long wo0, long wo1, long wo2,
    const void* __restrict__ X0, const void* __restrict__ X1, long xstride,
    const float* __restrict__ lnw, const float* __restrict__ lnb,
    float* __restrict__ Y0, float* __restrict__ Y1, float* __restrict__ Y2, long ystride,
    float* __restrict__ psum, float* __restrict__ pmax)
{
    extern __shared__ __align__(16) char smem[];
    uint32_t sX_hi = smem_u32(smem);
    uint32_t sX_lo = sX_hi + XT_BYTES;
    uint32_t sW_hi = sX_lo + XT_BYTES;
    uint32_t sW_lo = sW_hi + WT_BYTES;
    float* statsS = (float*)(smem + MM_SMEM);
    float* statsQ = statsS + 1024;
    float* muS    = statsQ + 1024;
    float* rsS    = muS + 128;

    const int tid = threadIdx.x;
    const int wid = tid >> 5, lane = tid & 31;
    const int bi = blockIdx.z;
    const int mh = blockIdx.y;
    const int p0 = blockIdx.x * 128;

    const int wm = wid & 1, wn = wid >> 1;
    const int m0 = wm * 32, n0 = wn * 32;
    const int ar = (lane & 7) + ((lane >> 3) & 1) * 8;
    const int ac = ((lane >> 4) & 1) * 8;
    const uint32_t offW = (uint32_t)((m0 + ar) * LDA + ac) * 2;
    const uint32_t offX = (uint32_t)(ar * LDA + n0 + ac) * 2;

    float C[2][4][4];
    if (KPASS > 1) {
        #pragma unroll
        for (int mt = 0; mt < 2; mt++)
            #pragma unroll
            for (int nt = 0; nt < 4; nt++)
                #pragma unroll
                for (int e = 0; e < 4; e++) C[mt][nt][e] = 0.f;
    }

    const int WROW = 128 * KPASS;

    #pragma unroll
    for (int pass = 0; pass < KPASS; pass++) {
        if (pass > 0) __syncthreads();

        if (PRESPLIT) {
            const unsigned short* Xh =
                (const unsigned short*)((pass == 0) ? X0 : X1) + (long)bi * xstride;
            const unsigned short* Xl = Xh + ELEMS;
            #pragma unroll
            for (int it = 0; it < 16; it++) {
                int idx = (it * 256 + tid) * 4;
                int kk = idx >> 7, nn = idx & 127;
                long src = (long)kk * PP + p0 + nn;
                uint2 h = *(const uint2*)&Xh[src];
                uint2 l = *(const uint2*)&Xl[src];
                uint32_t off = (uint32_t)(kk * LDA + nn) * 2;
                asm volatile("st.shared.v2.b32 [%0], {%1,%2};" :: "r"(sX_hi + off), "r"(h.x), "r"(h.y));
                asm volatile("st.shared.v2.b32 [%0], {%1,%2};" :: "r"(sX_lo + off), "r"(l.x), "r"(l.y));
            }
        } else {
            const float* Xsrc = (const float*)((pass == 0) ? X0 : X1) + (long)bi * xstride;
            if (LNIN) {
                float4 s4 = make_float4(0.f,0.f,0.f,0.f), q4 = make_float4(0.f,0.f,0.f,0.f);
                #pragma unroll
                for (int it = 0; it < 16; it++) {
                    int idx = (it * 256 + tid) * 4;
                    int kk = idx >> 7, nn = idx & 127;
                    float4 v = *(const float4*)&Xsrc[(long)kk * PP + p0 + nn];
                    s4.x += v.x; s4.y += v.y; s4.z += v.z; s4.w += v.w;
                    q4.x += v.x*v.x; q4.y += v.y*v.y; q4.z += v.z*v.z; q4.w += v.w*v.w;
                }
                {
                    int nn = (tid & 31) * 4;
                    *(float4*)&statsS[wid * 128 + nn] = s4;
                    *(float4*)&statsQ[wid * 128 + nn] = q4;
                }
                __syncthreads();
                if (tid < 128) {
                    float s = 0.f, q2 = 0.f;
                    #pragma unroll
                    for (int g = 0; g < 8; g++) { s += statsS[g * 128 + tid]; q2 += statsQ[g * 128 + tid]; }
                    float mu = s * (1.0f / 128.0f);
                    float var = q2 * (1.0f / 128.0f) - mu * mu;
                    muS[tid] = mu;
                    rsS[tid] = rsqrtf(var + 1e-5f);
                }
                __syncthreads();
                #pragma unroll
                for (int it = 0; it < 16; it++) {
                    int idx = (it * 256 + tid) * 4;
                    int kk = idx >> 7, nn = idx & 127;
                    float4 v = *(const float4*)&Xsrc[(long)kk * PP + p0 + nn];
                    float wc = __ldg(&lnw[kk]), bc = __ldg(&lnb[kk]);
                    v.x = (v.x - muS[nn + 0]) * rsS[nn + 0] * wc + bc;
                    v.y = (v.y - muS[nn + 1]) * rsS[nn + 1] * wc + bc;
                    v.z = (v.z - muS[nn + 2]) * rsS[nn + 2] * wc + bc;
                    v.w = (v.w - muS[nn + 3]) * rsS[nn + 3] * wc + bc;
                    uint32_t h0, l0, h1, l1;
                    split2(v.x, v.y, h0, l0);
                    split2(v.z, v.w, h1, l1);
                    uint32_t off = (uint32_t)(kk * LDA + nn) * 2;
                    asm volatile("st.shared.v2.b32 [%0], {%1,%2};" :: "r"(sX_hi + off), "r"(h0), "r"(h1));
                    asm volatile("st.shared.v2.b32 [%0], {%1,%2};" :: "r"(sX_lo + off), "r"(l0), "r"(l1));
                }
            } else {
                #pragma unroll
                for (int it = 0; it < 16; it++) {
                    int idx = (it * 256 + tid) * 4;
                    int kk = idx >> 7, nn = idx & 127;
                    float4 v = *(const float4*)&Xsrc[(long)kk * PP + p0 + nn];
                    uint32_t h0, l0, h1, l1;
                    split2(v.x, v.y, h0, l0);
                    split2(v.z, v.w, h1, l1);
                    uint32_t off = (uint32_t)(kk * LDA + nn) * 2;
                    asm volatile("st.shared.v2.b32 [%0], {%1,%2};" :: "r"(sX_hi + off), "r"(h0), "r"(h1));
                    asm volatile("st.shared.v2.b32 [%0], {%1,%2};" :: "r"(sX_lo + off), "r"(l0), "r"(l1));
                }
            }
        }

        #pragma unroll
        for (int s = 0; s < NSET; s++) {
            if (pass > 0 || s > 0) __syncthreads();
            const long wo = (s == 0) ? wo0 : ((s == 1) ? wo1 : wo2);
            #pragma unroll
            for (int it = 0; it < 8; it++) {
                int idx = (it * 256 + tid) * 4;
                int co = idx >> 7, k = idx & 127;
                long src = wo + (long)(mh * 64 + co) * WROW + pass * 128 + k;
                uint2 h = *(const uint2*)&WHI[src];
                uint2 l = *(const uint2*)&WLO[src];
                uint32_t off = (uint32_t)(co * LDA + k) * 2;
                asm volatile("st.shared.v2.b32 [%0], {%1,%2};" :: "r"(sW_hi + off), "r"(h.x), "r"(h.y));
                asm volatile("st.shared.v2.b32 [%0], {%1,%2};" :: "r"(sW_lo + off), "r"(l.x), "r"(l.y));
            }
            __syncthreads();

            if (KPASS == 1) {
                #pragma unroll
                for (int mt = 0; mt < 2; mt++)
                    #pragma unroll
                    for (int nt = 0; nt < 4; nt++)
                        #pragma unroll
                        for (int e = 0; e < 4; e++) C[mt][nt][e] = 0.f;
            }

            #pragma unroll
            for (int kk = 0; kk < 8; kk++) {
                int k0 = kk * 16;
                uint32_t ah[2][4], al[2][4];
                #pragma unroll
                for (int mt = 0; mt < 2; mt++) {
                    uint32_t o = offW + (uint32_t)(mt * 16 * LDA + k0) * 2;
                    ldsm_x4(ah[mt], sW_hi + o);
                    ldsm_x4(al[mt], sW_lo + o);
                }
                uint32_t bh[2][4], bl[2][4];
                #pragma unroll
                for (int bt = 0; bt < 2; bt++) {
                    uint32_t o = offX + (uint32_t)(k0 * LDA + bt * 16) * 2;
                    ldsm_x4_t(bh[bt], sX_hi + o);
                    ldsm_x4_t(bl[bt], sX_lo + o);
                }
                #pragma unroll
                for (int mt = 0; mt < 2; mt++)
                    #pragma unroll
                    for (int nt = 0; nt < 4; nt++) {
                        uint32_t b0h = bh[nt >> 1][(nt & 1) * 2], b1h = bh[nt >> 1][(nt & 1) * 2 + 1];
                        uint32_t b0l = bl[nt >> 1][(nt & 1) * 2], b1l = bl[nt >> 1][(nt & 1) * 2 + 1];
                        mma_bf16(C[mt][nt], ah[mt], b0h, b1h);
                        mma_bf16(C[mt][nt], ah[mt], b0l, b1l);
                        mma_bf16(C[mt][nt], al[mt], b0h, b1h);
                    }
            }

            if (KPASS == 1 && STORE) {
                float* Yb = ((s == 0) ? Y0 : ((s == 1) ? Y1 : Y2)) + (long)bi * ystride;
                const int g = lane >> 2, i2 = (lane & 3) * 2;
                #pragma unroll
                for (int mt = 0; mt < 2; mt++) {
                    int row0 = mh * 64 + m0 + mt * 16 + g;
                    #pragma unroll
                    for (int nt = 0; nt < 4; nt++) {
                        int p = p0 + n0 + nt * 8 + i2;
                        float2 o0 = make_float2(C[mt][nt][0], C[mt][nt][1]);
                        float2 o1 = make_float2(C[mt][nt][2], C[mt][nt][3]);
                        if (GOUT) {
                            o0.x = gelu_f(o0.x); o0.y = gelu_f(o0.y);
                            o1.x = gelu_f(o1.x); o1.y = gelu_f(o1.y);
                        }
                        *(float2*)&Yb[(long)row0 * PP + p]       = o0;
                        *(float2*)&Yb[(long)(row0 + 8) * PP + p] = o1;
                    }
                }
            }
        }
    }

    if (POOL) {
        __syncthreads();
        float* ps = (float*)smem;
        float* pm = ps + 256;
        const int g = lane >> 2;
        #pragma unroll
        for (int mt = 0; mt < 2; mt++) {
            float s0 = 0.f, s1 = 0.f, m0v = -INFINITY, m1v = -INFINITY;
            #pragma unroll
            for (int nt = 0; nt < 4; nt++) {
                s0 += C[mt][nt][0] + C[mt][nt][1];
                m0v = fmaxf(m0v, fmaxf(C[mt][nt][0], C[mt][nt][1]));
                s1 += C[mt][nt][2] + C[mt][nt][3];
                m1v = fmaxf(m1v, fmaxf(C[mt][nt][2], C[mt][nt][3]));
            }
            #pragma unroll
            for (int o = 1; o <= 2; o <<= 1) {
                s0 += __shfl_xor_sync(0xffffffffu, s0, o);
                s1 += __shfl_xor_sync(0xffffffffu, s1, o);
                m0v = fmaxf(m0v, __shfl_xor_sync(0xffffffffu, m0v, o));
                m1v = fmaxf(m1v, __shfl_xor_sync(0xffffffffu, m1v, o));
            }
            if ((lane & 3) == 0) {
                int r0 = m0 + mt * 16 + g;
                ps[r0 * 4 + wn] = s0;       pm[r0 * 4 + wn] = m0v;
                ps[(r0 + 8) * 4 + wn] = s1; pm[(r0 + 8) * 4 + wn] = m1v;
            }
        }
        __syncthreads();
        if (tid < 64) {
            float s = ps[tid*4] + ps[tid*4+1] + ps[tid*4+2] + ps[tid*4+3];
            float m = fmaxf(fmaxf(pm[tid*4], pm[tid*4+1]), fmaxf(pm[tid*4+2], pm[tid*4+3]));
            long ch = (long)(bi * CC + mh * 64 + tid);
            psum[ch * NBX + blockIdx.x] = s;
            pmax[ch * NBX + blockIdx.x] = m;
        }
    }
}

// ---------------- multi-tensor depthwise 3x3 pad 1: 4x4 px/thread ----------------
// OUT mode per z: GSPLIT -> gelu+split all; QKSPLIT -> split (no gelu) for z<2, float for z=2.
template<int SQMASK, bool GSPLIT, bool QKSPLIT>
__global__ void __launch_bounds__(256) dwm_kernel(
    const float* __restrict__ x0, const float* __restrict__ x1, const float* __restrict__ x2,
    const float* __restrict__ w0, const float* __restrict__ w1, const float* __restrict__ w2,
    void* __restrict__ y0, void* __restrict__ y1, void* __restrict__ y2,
    float* __restrict__ sq0, float* __restrict__ sq1) {
    int i = blockIdx.x * 256 + threadIdx.x;
    int bc = blockIdx.y;
    int z  = blockIdx.z;
    const float* x = (z == 0) ? x0 : ((z == 1) ? x1 : x2);
    const float* w = (z == 0) ? w0 : ((z == 1) ? w1 : w2);
    void* yout     = (z == 0) ? y0 : ((z == 1) ? y1 : y2);
    const bool doSQ = (SQMASK >> z) & 1;

    int rq = i / 48, cg = i % 48;
    int y0r = rq * 4, xx = cg * 4;
    const float* xp = x + (size_t)bc * PP;
    const float* wc = w + (bc % CC) * 9;
    float kw[3][3];
    #pragma unroll
    for (int j = 0; j < 9; j++) kw[j/3][j%3] = wc[j];

    float4 c[6]; float lf[6], rt[6];
    #pragma unroll
    for (int r = 0; r < 6; r++) {
        int sy = y0r - 1 + r;
        bool ok = (unsigned)sy < HIMG;
        const float* row = xp + sy * WIMG + xx;
        c[r]  = ok ? *(const float4*)row : make_float4(0.f, 0.f, 0.f, 0.f);
        lf[r] = (ok && xx > 0) ? row[-1] : 0.f;
        rt[r] = (ok && xx + 4 < WIMG) ? row[4] : 0.f;
    }

    float4 a[4];
    #pragma unroll
    for (int r = 0; r < 4; r++) a[r] = make_float4(0.f, 0.f, 0.f, 0.f);
    #pragma unroll
    for (int ky = 0; ky < 3; ky++) {
        float k0 = kw[ky][0], k1 = kw[ky][1], k2 = kw[ky][2];
        #pragma unroll
        for (int r = 0; r < 4; r++) {
            float4 cc = c[r + ky]; float l = lf[r + ky], rr = rt[r + ky];
            a[r].x += k0*l    + k1*cc.x + k2*cc.y;
            a[r].y += k0*cc.x + k1*cc.y + k2*cc.z;
            a[r].z += k0*cc.y + k1*cc.z + k2*cc.w;
            a[r].w += k0*cc.z + k1*cc.w + k2*rr;
        }
    }

    const bool dosplit = GSPLIT || (QKSPLIT && z < 2);
    if (dosplit) {
        unsigned short* yh = (unsigned short*)yout;
        unsigned short* yl = yh + ELEMS;
        #pragma unroll
        for (int r = 0; r < 4; r++) {
            float gx = a[r].x, gy = a[r].y, gz = a[r].z, gw = a[r].w;
            if (GSPLIT) { gx = gelu_f(gx); gy = gelu_f(gy); gz = gelu_f(gz); gw = gelu_f(gw); }
            uint32_t h0, l0, h1, l1;
            split2(gx, gy, h0, l0);
            split2(gz, gw, h1, l1);
            size_t o = (size_t)bc * PP + (y0r + r) * WIMG + xx;
            *(uint2*)&yh[o] = make_uint2(h0, h1);
            *(uint2*)&yl[o] = make_uint2(l0, l1);
        }
    } else {
        float* yp = (float*)yout + (size_t)bc * PP;
        #pragma unroll
        for (int r = 0; r < 4; r++)
            *(float4*)&yp[(y0r + r) * WIMG + xx] = a[r];
    }

    if (SQMASK) {
        if (doSQ) {
            float s = 0.f;
            #pragma unroll
            for (int r = 0; r < 4; r++)
                s += a[r].x*a[r].x + a[r].y*a[r].y + a[r].z*a[r].z + a[r].w*a[r].w;
            __shared__ float red[256];
            red[threadIdx.x] = s; __syncthreads();
            for (int o = 128; o > 0; o >>= 1) {
                if (threadIdx.x < o) red[threadIdx.x] += red[threadIdx.x + o];
                __syncthreads();
            }
            if (threadIdx.x == 0) {
                float* sqp = (z == 0) ? sq0 : sq1;
                sqp[bc * NDW + blockIdx.x] = red[0];
            }
        }
    }
}

// ---------------- Gram partials via HMMA (pre-split q/k, copy staging, 3 CTAs/SM) ----------------
#define LDK 136
#define GT_BYTES (64*LDK*2)
#define GR_SMEM (4*GT_BYTES)
__global__ void __launch_bounds__(256, 3) gram_mma(const unsigned short* __restrict__ q,
                                                   const unsigned short* __restrict__ k,
                                                   float* __restrict__ part) {
    extern __shared__ __align__(16) char smem[];
    uint32_t sb = smem_u32(smem);
    uint32_t sQ_hi = sb, sQ_lo = sb + GT_BYTES;
    uint32_t sK_hi = sb + 2*GT_BYTES, sK_lo = sb + 3*GT_BYTES;

    const int tid = threadIdx.x;
    const int wid = tid >> 5, lane = tid & 31;
    const int ch = blockIdx.x, bn = blockIdx.y;
    const size_t base = (size_t)bn * HD * PP + (size_t)ch * CPX2;
    const unsigned short* qh = q + base;
    const unsigned short* ql = q + ELEMS + base;
    const unsigned short* kh = k + base;
    const unsigned short* kl = k + ELEMS + base;

    const int wm = wid & 1, wn = wid >> 1;
    const int m0 = wm * 32, n0 = wn * 16;
    const int ar = (lane & 7) + ((lane >> 3) & 1) * 8;
    const int ac = ((lane >> 4) & 1) * 8;
    const uint32_t offA = (uint32_t)((m0 + ar) * LDK + ac) * 2;
    const uint32_t offB = (uint32_t)((n0 + ar) * LDK + ac) * 2;

    float C[2][2][4];
    #pragma unroll
    for (int mt = 0; mt < 2; mt++)
        #pragma unroll
        for (int nt = 0; nt < 2; nt++)
            #pragma unroll
            for (int e = 0; e < 4; e++) C[mt][nt][e] = 0.f;

    for (int t = 0; t < CPX2 / 128; t++) {
        if (t > 0) __syncthreads();
        #pragma unroll
        for (int it = 0; it < 8; it++) {
            int idx = (it * 256 + tid) * 4;
            int r = idx >> 7, n = idx & 127;
            size_t src = (size_t)r * PP + t * 128 + n;
            uint2 h = *(const uint2*)&qh[src];
            uint2 l = *(const uint2*)&ql[src];
            uint32_t off = (uint32_t)(r * LDK + n) * 2;
            asm volatile("st.shared.v2.b32 [%0], {%1,%2};" :: "r"(sQ_hi + off), "r"(h.x), "r"(h.y));
            asm volatile("st.shared.v2.b32 [%0], {%1,%2};" :: "r"(sQ_lo + off), "r"(l.x), "r"(l.y));
        }
        #pragma unroll
        for (int it = 0; it < 8; it++) {
            int idx = (it * 256 + tid) * 4;
            int r = idx >> 7, n = idx & 127;
            size_t src = (size_t)r * PP + t * 128 + n;
            uint2 h = *(const uint2*)&kh[src];
            uint2 l = *(const uint2*)&kl[src];
            uint32_t off = (uint32_t)(r * LDK + n) * 2;
            asm volatile("st.shared.v2.b32 [%0], {%1,%2};" :: "r"(sK_hi + off), "r"(h.x), "r"(h.y));
            asm volatile("st.shared.v2.b32 [%0], {%1,%2};" :: "r"(sK_lo + off), "r"(l.x), "r"(l.y));
        }
        __syncthreads();

        #pragma unroll
        for (int kk = 0; kk < 8; kk++) {
            int k0 = kk * 16;
            uint32_t ah[2][4], al[2][4];
            #pragma unroll
            for (int mt = 0; mt < 2; mt++) {
                uint32_t o = offA + (uint32_t)(mt * 16 * LDK + k0) * 2;
                ldsm_x4(ah[mt], sQ_hi + o);
                ldsm_x4(al[mt], sQ_lo + o);
            }
            uint32_t bh[4], bl[4];
            ldsm_x4(bh, sK_hi + offB + (uint32_t)k0 * 2);
            ldsm_x4(bl, sK_lo + offB + (uint32_t)k0 * 2);
            #pragma unroll
            for (int mt = 0; mt < 2; mt++) {
                mma_bf16(C[mt][0], ah[mt], bh[0], bh[2]);
                mma_bf16(C[mt][1], ah[mt], bh[1], bh[3]);
                mma_bf16(C[mt][0], ah[mt], bl[0], bl[2]);
                mma_bf16(C[mt][1], ah[mt], bl[1], bl[3]);
                mma_bf16(C[mt][0], al[mt], bh[0], bh[2]);
                mma_bf16(C[mt][1], al[mt], bh[1], bh[3]);
            }
        }
    }

    float* pb = part + (((size_t)bn * NCH2 + ch) * HD) * HD;
    const int g = lane >> 2, i2 = (lane & 3) * 2;
    #pragma unroll
    for (int mt = 0; mt < 2; mt++) {
        int i = m0 + mt * 16 + g;
        #pragma unroll
        for (int nt = 0; nt < 2; nt++) {
            int j = n0 + nt * 8 + i2;
            pb[i * HD + j]       = C[mt][nt][0];
            pb[i * HD + j + 1]   = C[mt][nt][1];
            pb[(i + 8) * HD + j]     = C[mt][nt][2];
            pb[(i + 8) * HD + j + 1] = C[mt][nt][3];
        }
    }
}

// ---------------- norms (from dw sumsq partials) + reduce + softmax ----------------
__global__ void attn_softmax(const float* __restrict__ part,
                             const float* __restrict__ sqq, const float* __restrict__ sqk,
                             const float* __restrict__ scale,
                             float* __restrict__ attnw_out, float* __restrict__ a) {
    __shared__ float nqS[HD], nkS[HD];
    int bn = blockIdx.x;
    int n = bn % NH;
    int tid = threadIdx.x;
    int warp = tid / 32, lane = tid % 32;

    if (tid < 128) {
        int i = tid & 63;
        const float* sp = (tid < 64) ? sqq : sqk;
        float s = 0.f;
        #pragma unroll
        for (int j = 0; j < NDW; j++) s += sp[(bn * HD + i) * NDW + j];
        float nv = fmaxf(sqrtf(s), 1e-12f);
        if (tid < 64) nqS[i] = nv; else nkS[i] = nv;
    }
    __syncthreads();

    float sc = scale[n];
    for (int i = warp; i < HD; i += 8) {
        float v[2];
        #pragma unroll
        for (int h = 0; h < 2; h++) {
            int j = lane + 32 * h;
            float s = 0.f;
            for (int ch = 0; ch < NCH2; ch++)
                s += part[(((size_t)bn * NCH2 + ch) * HD + i) * HD + j];
            s = s * sc / (nqS[i] * nkS[j]);
            attnw_out[((size_t)bn * HD + i) * HD + j] = s;
            v[h] = s;
        }
        float m = fmaxf(v[0], v[1]);
        #pragma unroll
        for (int o = 16; o; o >>= 1) m = fmaxf(m, __shfl_xor_sync(0xffffffffu, m, o));
        float e0 = expf(v[0] - m), e1 = expf(v[1] - m);
        float s = e0 + e1;
        #pragma unroll
        for (int o = 16; o; o >>= 1) s += __shfl_xor_sync(0xffffffffu, s, o);
        float inv = 1.0f / s;
        a[((size_t)bn * HD + i) * HD + lane]      = e0 * inv;
        a[((size_t)bn * HD + i) * HD + lane + 32] = e1 * inv;
    }
}

// ---------------- fused a@v + channel-LN ----------------
#define AV_SMEM (8192*4 + 128*132*4 + (2*1024 + 256)*4)
__global__ void __launch_bounds__(256) avln_kernel(
    const float* __restrict__ a, const float* __restrict__ v,
    const float* __restrict__ lnw, const float* __restrict__ lnb,
    float* __restrict__ t)
{
    extern __shared__ __align__(16) float dsm[];
    float* As = dsm;
    float* Vs = As + 8192;
    float* redS = Vs + 128*132;
    float* redQ = redS + 1024;
    float* muA  = redQ + 1024;
    float* rsA  = muA + 128;

    const int tid = threadIdx.x;
    const int bi = blockIdx.y;
    const int p0 = blockIdx.x * 128;

    const float* ab = a + (size_t)bi * 2 * 4096;
    #pragma unroll
    for (int it = 0; it < 8; it++) {
        int idx = (it * 256 + tid) * 4;
        *(float4*)&As[idx] = *(const float4*)&ab[idx];
    }
    const float* vb = v + (size_t)bi * CC * PP;
    #pragma unroll
    for (int it = 0; it < 16; it++) {
        int idx = it * 256 + tid;
        int row = idx >> 5, n4 = idx & 31;
        *(float4*)&Vs[row * 132 + n4 * 4] = *(const float4*)&vb[(size_t)row * PP + p0 + n4 * 4];
    }
    __syncthreads();

    const int px4 = tid & 31;
    const int cg = tid >> 5;
    const int h = cg >> 2;
    const int cbase = cg * 16;
    const float* Ah = As + h * 4096;

    float4 acc[16];
    #pragma unroll
    for (int cl = 0; cl < 16; cl++) acc[cl] = make_float4(0.f, 0.f, 0.f, 0.f);

    #pragma unroll
    for (int j4 = 0; j4 < 16; j4++) {
        float4 vv0 = *(float4*)&Vs[(h*64 + j4*4 + 0) * 132 + px4*4];
        float4 vv1 = *(float4*)&Vs[(h*64 + j4*4 + 1) * 132 + px4*4];
        float4 vv2 = *(float4*)&Vs[(h*64 + j4*4 + 2) * 132 + px4*4];
        float4 vv3 = *(float4*)&Vs[(h*64 + j4*4 + 3) * 132 + px4*4];
        #pragma unroll
        for (int cl = 0; cl < 16; cl++) {
            int i = (cbase + cl) & 63;
            float4 a4 = *(float4*)&Ah[i * 64 + j4 * 4];
            acc[cl].x += a4.x*vv0.x + a4.y*vv1.x + a4.z*vv2.x + a4.w*vv3.x;
            acc[cl].y += a4.x*vv0.y + a4.y*vv1.y + a4.z*vv2.y + a4.w*vv3.y;
            acc[cl].z += a4.x*vv0.z + a4.y*vv1.z + a4.z*vv2.z + a4.w*vv3.z;
            acc[cl].w += a4.x*vv0.w + a4.y*vv1.w + a4.z*vv2.w + a4.w*vv3.w;
        }
    }

    float4 s4 = make_float4(0.f,0.f,0.f,0.f), q4 = make_float4(0.f,0.f,0.f,0.f);
    #pragma unroll
    for (int cl = 0; cl < 16; cl++) {
        s4.x += acc[cl].x; s4.y += acc[cl].y; s4.z += acc[cl].z; s4.w += acc[cl].w;
        q4.x += acc[cl].x*acc[cl].x; q4.y += acc[cl].y*acc[cl].y;
        q4.z += acc[cl].z*acc[cl].z; q4.w += acc[cl].w*acc[cl].w;
    }
    *(float4*)&redS[cg * 128 + px4 * 4] = s4;
    *(float4*)&redQ[cg * 128 + px4 * 4] = q4;
    __syncthreads();
    if (tid < 128) {
        float s = 0.f, q2 = 0.f;
        #pragma unroll
        for (int g = 0; g < 8; g++) { s += redS[g * 128 + tid]; q2 += redQ[g * 128 + tid]; }
        float mu = s * (1.0f / 128.0f);
        float var = q2 * (1.0f / 128.0f) - mu * mu;
        muA[tid] = mu;
        rsA[tid] = rsqrtf(var + 1e-5f);
    }
    __syncthreads();

    float4 mu4 = *(float4*)&muA[px4 * 4];
    float4 rs4 = *(float4*)&rsA[px4 * 4];
    float* tb = t + (size_t)bi * CC * PP;
    #pragma unroll
    for (int cl = 0; cl < 16; cl++) {
        int c = cbase + cl;
        float w = __ldg(&lnw[c]), b = __ldg(&lnb[c]);
        float4 o;
        o.x = (acc[cl].x - mu4.x) * rs4.x * w + b;
        o.y = (acc[cl].y - mu4.y) * rs4.y * w + b;
        o.z = (acc[cl].z - mu4.z) * rs4.z * w + b;
        o.w = (acc[cl].w - mu4.w) * rs4.w * w + b;
        *(float4*)&tb[(size_t)c * PP + p0 + px4 * 4] = o;
    }
}

// ---------------- pool partial reduce + ChannelGate ----------------
__global__ void gate_pool_kernel(const float* __restrict__ psum, const float* __restrict__ pmax,
                                 const float* __restrict__ w1, const float* __restrict__ b1,
                                 const float* __restrict__ w2, const float* __restrict__ b2,
                                 float* __restrict__ out) {
    __shared__ float sa[CC], sm_[CC], ha[8], hm[8];
    int c = threadIdx.x;
    for (int b = 0; b < BB; b++) {
        float s = 0.f, m = -INFINITY;
        long base = (long)(b * CC + c) * NBX;
        for (int i = 0; i < NBX; i++) {
            s += psum[base + i];
            m = fmaxf(m, pmax[base + i]);
        }
        sa[c] = s * (1.0f / PP);
        sm_[c] = m;
        __syncthreads();
        if (c < 8) {
            float xa = b1[c], xm = b1[c];
            for (int cc = 0; cc < CC; cc++) {
                xa += w1[c*CC + cc] * sa[cc];
                xm += w1[c*CC + cc] * sm_[cc];
            }
            ha[c] = fmaxf(xa, 0.f);
            hm[c] = fmaxf(xm, 0.f);
        }
        __syncthreads();
        float xa = b2[c], xm = b2[c];
        #pragma unroll
        for (int j = 0; j < 8; j++) {
            xa += w2[c*8 + j] * ha[j];
            xm += w2[c*8 + j] * hm[j];
        }
        out[b*CC + c] = 1.0f / (1.0f + expf(-(xa + xm)));
        __syncthreads();
    }
}

// ---------------- host launch ----------------
static float* sym(const void* s) {
    void* p = nullptr;
    cudaGetSymbolAddress(&p, s);
    return (float*)p;
}

extern "C" void kernel_launch(void* const* d_in, const int* in_sizes, int n_in,
                              void* d_out, int out_size) {
    const float* x       = (const float*)d_in[0];
    const float* ln_in_w = (const float*)d_in[1];
    const float* ln_in_b = (const float*)d_in[2];
    const float* wq_pw   = (const float*)d_in[3];
    const float* wq_dw   = (const float*)d_in[4];
    const float* wk_pw   = (const float*)d_in[5];
    const float* wk_dw   = (const float*)d_in[6];
    const float* wv_pw   = (const float*)d_in[7];
    const float* wv_dw   = (const float*)d_in[8];
    const float* scale   = (const float*)d_in[9];
    const float* ln_o_w  = (const float*)d_in[10];
    const float* ln_o_b  = (const float*)d_in[11];
    const float* f1_pw   = (const float*)d_in[12];
    const float* f1_dw   = (const float*)d_in[13];
    const float* f2_pw   = (const float*)d_in[14];
    const float* f2_dw   = (const float*)d_in[15];
    const float* f_out   = (const float*)d_in[16];
    const float* g_w1    = (const float*)d_in[17];
    const float* g_b1    = (const float*)d_in[18];
    const float* g_w2    = (const float*)d_in[19];
    const float* g_b2    = (const float*)d_in[20];
    float* out = (float*)d_out;

    float* t  = sym(g_t);   float* t2 = sym(g_t2);  float* t3 = sym(g_t3);
    float* q  = sym(g_q);   float* k  = sym(g_k);   float* v  = sym(g_v);
    float* part = sym(g_part); float* a = sym(g_a);
    float* sqq = sym(g_sqq);   float* sqk = sym(g_sqk);
    float* psum = sym(g_psum); float* pmax = sym(g_pmax);
    unsigned short* whi = (unsigned short*)sym(g_whi);
    unsigned short* wlo = (unsigned short*)sym(g_wlo);

    auto qkv  = gemm_fused<1,3,true, false,false,false,true>;
    auto f1f2 = gemm_fused<1,2,false,false,true, false,true>;
    auto fout = gemm_fused<2,1,false,true, false,true, false>;
    cudaFuncSetAttribute(qkv,  cudaFuncAttributeMaxDynamicSharedMemorySize, MM_SMEM_LN);
    cudaFuncSetAttribute(f1f2, cudaFuncAttributeMaxDynamicSharedMemorySize, MM_SMEM);
    cudaFuncSetAttribute(fout, cudaFuncAttributeMaxDynamicSharedMemorySize, MM_SMEM);
    cudaFuncSetAttribute(gram_mma, cudaFuncAttributeMaxDynamicSharedMemorySize, GR_SMEM);
    cudaFuncSetAttribute(avln_kernel, cudaFuncAttributeMaxDynamicSharedMemorySize, AV_SMEM);

    const long SB = (long)CC * PP;
    dim3 gGrid(NBX, 2, BB);
    dim3 dwGrid3(NDW, BB*CC, 3);
    dim3 dwGrid2(NDW, BB*CC, 2);
    dim3 avGrid(NBX, BB);

    // 0) precompute weight hi/lo splits (single merged launch)
    wprep_all<<<(WTOT + 255)/256, 256>>>(wq_pw, wk_pw, wv_pw, f1_pw, f2_pw, f_out, whi, wlo);

    // 1) fused LN + QKV pointwise
    qkv<<<gGrid, 256, MM_SMEM_LN>>>(whi, wlo, OWQ, OWK, OWV, x, nullptr, SB,
                                    ln_in_w, ln_in_b, t, t2, t3, SB, nullptr, nullptr);
    // 2) depthwise q/k/v in ONE launch; q,k stored as split bf16 planes, v float
    dwm_kernel<3, false, true><<<dwGrid3, 256>>>(t, t2, t3, wq_dw, wk_dw, wv_dw,
                                                 q, k, v, sqq, sqk);
    // 3) Gram (HMMA, pre-split q/k, 3 CTAs/SM) + softmax
    gram_mma<<<dim3(NCH2, BNH), 256, GR_SMEM>>>((const unsigned short*)q,
                                                (const unsigned short*)k, part);
    attn_softmax<<<BNH, 256>>>(part, sqq, sqk, scale, out + BB*CC, a);
    // 4) fused a@v + LN -> t
    avln_kernel<<<avGrid, 256, AV_SMEM>>>(a, v, ln_o_w, ln_o_b, t);
    // 5) fused f1+f2 pointwise (GELU out) -> t2, t3
    f1f2<<<gGrid, 256, MM_SMEM>>>(whi, wlo, OF1, OF2, 0, t, nullptr, SB,
                                  nullptr, nullptr, t2, t3, nullptr, SB, nullptr, nullptr);
    // 6) depthwise FFN branches in ONE launch -> gelu'd split bf16 planes
    dwm_kernel<0, true, false><<<dwGrid2, 256>>>(t2, t3, nullptr, f1_dw, f2_dw, nullptr,
                                                 q, k, nullptr, nullptr, nullptr);
    // 7) f_out (pre-split X, K=256) -> pool partials only
    fout<<<gGrid, 256, MM_SMEM>>>(whi, wlo, OFO, 0, 0, q, k, SB,
                                  nullptr, nullptr, nullptr, nullptr, nullptr, SB, psum, pmax);
    // 8) ChannelGate
    gate_pool_kernel<<<1, 128>>>(psum, pmax, g_w1, g_b1, g_w2, g_b2, out);
}

// round 17
// speedup vs baseline: 1.0436x; 1.0159x over previous
#include <cuda_runtime.h>
#include <cuda_bf16.h>
#include <math.h>
#include <stdint.h>

// ---------------- problem constants ----------------
#define BB 4
#define CC 128
#define HIMG 192
#define WIMG 192
#define PP (HIMG*WIMG)          // 36864
#define NH 2
#define HD 64
#define BNH (BB*NH)             // 8
#define NBX (PP/128)            // 288
#define NDW 9                   // dw blocks per plane (16 px/thread)
#define NCH2 48                 // gram chunks per (b,head)
#define CPX2 (PP/NCH2)          // 768

#define ELEMS ((size_t)BB*CC*PP)

// weight-split offsets (elements)
#define OWQ 0
#define OWK 16384
#define OWV 32768
#define OF1 49152
#define OF2 65536
#define OFO 81920
#define WTOT 114688

// ---------------- scratch ----------------
__device__ float g_t [ELEMS];
__device__ float g_t2[ELEMS];
__device__ float g_t3[ELEMS];
__device__ float g_q [ELEMS];   // ushort hi/lo planes (attention q, FFN o1)
__device__ float g_k [ELEMS];   // ushort hi/lo planes (attention k, FFN o2)
__device__ float g_v [ELEMS];
__device__ float g_part[(size_t)BNH*NCH2*HD*HD];
__device__ float g_a[BNH*HD*HD];
__device__ float g_sqq[BB*CC*NDW];
__device__ float g_sqk[BB*CC*NDW];
__device__ float g_psum[BB*CC*NBX];
__device__ float g_pmax[BB*CC*NBX];
__device__ unsigned short g_whi[WTOT];
__device__ unsigned short g_wlo[WTOT];

__device__ __forceinline__ float gelu_f(float x) {
    return 0.5f * x * (1.0f + erff(x * 0.70710678118654752f));
}

// ================= mma.sync helpers =================
__device__ __forceinline__ uint32_t smem_u32(const void* p) {
    uint32_t a;
    asm("{ .reg .u64 t; cvta.to.shared.u64 t, %1; cvt.u32.u64 %0, t; }" : "=r"(a) : "l"(p));
    return a;
}
__device__ __forceinline__ void ldsm_x4(uint32_t* r, uint32_t addr) {
    asm volatile("ldmatrix.sync.aligned.m8n8.x4.shared.b16 {%0,%1,%2,%3}, [%4];"
        : "=r"(r[0]), "=r"(r[1]), "=r"(r[2]), "=r"(r[3]) : "r"(addr));
}
__device__ __forceinline__ void ldsm_x4_t(uint32_t* r, uint32_t addr) {
    asm volatile("ldmatrix.sync.aligned.m8n8.x4.trans.shared.b16 {%0,%1,%2,%3}, [%4];"
        : "=r"(r[0]), "=r"(r[1]), "=r"(r[2]), "=r"(r[3]) : "r"(addr));
}
__device__ __forceinline__ void mma_bf16(float* c, const uint32_t* a, uint32_t b0, uint32_t b1) {
    asm volatile(
        "mma.sync.aligned.m16n8k16.row.col.f32.bf16.bf16.f32 "
        "{%0,%1,%2,%3}, {%4,%5,%6,%7}, {%8,%9}, {%0,%1,%2,%3};"
        : "+f"(c[0]), "+f"(c[1]), "+f"(c[2]), "+f"(c[3])
        : "r"(a[0]), "r"(a[1]), "r"(a[2]), "r"(a[3]), "r"(b0), "r"(b1));
}
__device__ __forceinline__ void split2(float x, float y, uint32_t& hi, uint32_t& lo) {
    __nv_bfloat16 hx = __float2bfloat16_rn(x);
    __nv_bfloat16 hy = __float2bfloat16_rn(y);
    __nv_bfloat16 lx = __float2bfloat16_rn(x - __bfloat162float(hx));
    __nv_bfloat16 ly = __float2bfloat16_rn(y - __bfloat162float(hy));
    hi = (uint32_t)__bfloat16_as_ushort(hx) | ((uint32_t)__bfloat16_as_ushort(hy) << 16);
    lo = (uint32_t)__bfloat16_as_ushort(lx) | ((uint32_t)__bfloat16_as_ushort(ly) << 16);
}

// ---------------- merged weight split precompute (one launch) ----------------
__global__ void wprep_all(const float* __restrict__ wq, const float* __restrict__ wk,
                          const float* __restrict__ wv, const float* __restrict__ f1,
                          const float* __restrict__ f2, const float* __restrict__ fo,
                          unsigned short* __restrict__ hi, unsigned short* __restrict__ lo) {
    int i = blockIdx.x * 256 + threadIdx.x;
    if (i >= WTOT) return;
    const float* src; int off;
    if (i < OWK)      { src = wq; off = OWQ; }
    else if (i < OWV) { src = wk; off = OWK; }
    else if (i < OF1) { src = wv; off = OWV; }
    else if (i < OF2) { src = f1; off = OF1; }
    else if (i < OFO) { src = f2; off = OF2; }
    else              { src = fo; off = OFO; }
    float x = src[i - off];
    __nv_bfloat16 h = __float2bfloat16_rn(x);
    __nv_bfloat16 l = __float2bfloat16_rn(x - __bfloat162float(h));
    hi[i] = __bfloat16_as_ushort(h);
    lo[i] = __bfloat16_as_ushort(l);
}

// ============== fused HMMA pointwise GEMM (split-M: 64x128 tile, 2 CTAs/SM) ==============
#define LDA 136
#define XT_BYTES (128*LDA*2)
#define WT_BYTES (64*LDA*2)
#define MM_SMEM  (2*XT_BYTES + 2*WT_BYTES)     // 104448
#define MM_SMEM_LN (MM_SMEM + (2048 + 256)*4)  // 113664

template<int KPASS, int NSET, bool LNIN, bool PRESPLIT, bool GOUT, bool POOL, bool STORE>
__global__ void __launch_bounds__(256, 2) gemm_fused(
    const unsigned short* __restrict__ WHI, const unsigned short* __restrict__ WLO,
    long wo0, long wo1, long wo2,
    const void* __restrict__ X0, const void* __restrict__ X1, long xstride,
    const float* __restrict__ lnw, const float* __restrict__ lnb,
    float* __restrict__ Y0, float* __restrict__ Y1, float* __restrict__ Y2, long ystride,
    float* __restrict__ psum, float* __restrict__ pmax)
{
    extern __shared__ __align__(16) char smem[];
    uint32_t sX_hi = smem_u32(smem);
    uint32_t sX_lo = sX_hi + XT_BYTES;
    uint32_t sW_hi = sX_lo + XT_BYTES;
    uint32_t sW_lo = sW_hi + WT_BYTES;
    float* statsS = (float*)(smem + MM_SMEM);
    float* statsQ = statsS + 1024;
    float* muS    = statsQ + 1024;
    float* rsS    = muS + 128;

    const int tid = threadIdx.x;
    const int wid = tid >> 5, lane = tid & 31;
    const int bi = blockIdx.z;
    const int mh = blockIdx.y;
    const int p0 = blockIdx.x * 128;

    const int wm = wid & 1, wn = wid >> 1;
    const int m0 = wm * 32, n0 = wn * 32;
    const int ar = (lane & 7) + ((lane >> 3) & 1) * 8;
    const int ac = ((lane >> 4) & 1) * 8;
    const uint32_t offW = (uint32_t)((m0 + ar) * LDA + ac) * 2;
    const uint32_t offX = (uint32_t)(ar * LDA + n0 + ac) * 2;

    float C[2][4][4];
    if (KPASS > 1) {
        #pragma unroll
        for (int mt = 0; mt < 2; mt++)
            #pragma unroll
            for (int nt = 0; nt < 4; nt++)
                #pragma unroll
                for (int e = 0; e < 4; e++) C[mt][nt][e] = 0.f;
    }

    const int WROW = 128 * KPASS;

    #pragma unroll
    for (int pass = 0; pass < KPASS; pass++) {
        if (pass > 0) __syncthreads();

        if (PRESPLIT) {
            const unsigned short* Xh =
                (const unsigned short*)((pass == 0) ? X0 : X1) + (long)bi * xstride;
            const unsigned short* Xl = Xh + ELEMS;
            #pragma unroll
            for (int it = 0; it < 16; it++) {
                int idx = (it * 256 + tid) * 4;
                int kk = idx >> 7, nn = idx & 127;
                long src = (long)kk * PP + p0 + nn;
                uint2 h = *(const uint2*)&Xh[src];
                uint2 l = *(const uint2*)&Xl[src];
                uint32_t off = (uint32_t)(kk * LDA + nn) * 2;
                asm volatile("st.shared.v2.b32 [%0], {%1,%2};" :: "r"(sX_hi + off), "r"(h.x), "r"(h.y));
                asm volatile("st.shared.v2.b32 [%0], {%1,%2};" :: "r"(sX_lo + off), "r"(l.x), "r"(l.y));
            }
        } else {
            const float* Xsrc = (const float*)((pass == 0) ? X0 : X1) + (long)bi * xstride;
            if (LNIN) {
                float4 s4 = make_float4(0.f,0.f,0.f,0.f), q4 = make_float4(0.f,0.f,0.f,0.f);
                #pragma unroll
                for (int it = 0; it < 16; it++) {
                    int idx = (it * 256 + tid) * 4;
                    int kk = idx >> 7, nn = idx & 127;
                    float4 v = *(const float4*)&Xsrc[(long)kk * PP + p0 + nn];
                    s4.x += v.x; s4.y += v.y; s4.z += v.z; s4.w += v.w;
                    q4.x += v.x*v.x; q4.y += v.y*v.y; q4.z += v.z*v.z; q4.w += v.w*v.w;
                }
                {
                    int nn = (tid & 31) * 4;
                    *(float4*)&statsS[wid * 128 + nn] = s4;
                    *(float4*)&statsQ[wid * 128 + nn] = q4;
                }
                __syncthreads();
                if (tid < 128) {
                    float s = 0.f, q2 = 0.f;
                    #pragma unroll
                    for (int g = 0; g < 8; g++) { s += statsS[g * 128 + tid]; q2 += statsQ[g * 128 + tid]; }
                    float mu = s * (1.0f / 128.0f);
                    float var = q2 * (1.0f / 128.0f) - mu * mu;
                    muS[tid] = mu;
                    rsS[tid] = rsqrtf(var + 1e-5f);
                }
                __syncthreads();
                #pragma unroll
                for (int it = 0; it < 16; it++) {
                    int idx = (it * 256 + tid) * 4;
                    int kk = idx >> 7, nn = idx & 127;
                    float4 v = *(const float4*)&Xsrc[(long)kk * PP + p0 + nn];
                    float wc = __ldg(&lnw[kk]), bc = __ldg(&lnb[kk]);
                    v.x = (v.x - muS[nn + 0]) * rsS[nn + 0] * wc + bc;
                    v.y = (v.y - muS[nn + 1]) * rsS[nn + 1] * wc + bc;
                    v.z = (v.z - muS[nn + 2]) * rsS[nn + 2] * wc + bc;
                    v.w = (v.w - muS[nn + 3]) * rsS[nn + 3] * wc + bc;
                    uint32_t h0, l0, h1, l1;
                    split2(v.x, v.y, h0, l0);
                    split2(v.z, v.w, h1, l1);
                    uint32_t off = (uint32_t)(kk * LDA + nn) * 2;
                    asm volatile("st.shared.v2.b32 [%0], {%1,%2};" :: "r"(sX_hi + off), "r"(h0), "r"(h1));
                    asm volatile("st.shared.v2.b32 [%0], {%1,%2};" :: "r"(sX_lo + off), "r"(l0), "r"(l1));
                }
            } else {
                #pragma unroll
                for (int it = 0; it < 16; it++) {
                    int idx = (it * 256 + tid) * 4;
                    int kk = idx >> 7, nn = idx & 127;
                    float4 v = *(const float4*)&Xsrc[(long)kk * PP + p0 + nn];
                    uint32_t h0, l0, h1, l1;
                    split2(v.x, v.y, h0, l0);
                    split2(v.z, v.w, h1, l1);
                    uint32_t off = (uint32_t)(kk * LDA + nn) * 2;
                    asm volatile("st.shared.v2.b32 [%0], {%1,%2};" :: "r"(sX_hi + off), "r"(h0), "r"(h1));
                    asm volatile("st.shared.v2.b32 [%0], {%1,%2};" :: "r"(sX_lo + off), "r"(l0), "r"(l1));
                }
            }
        }

        #pragma unroll
        for (int s = 0; s < NSET; s++) {
            if (pass > 0 || s > 0) __syncthreads();
            const long wo = (s == 0) ? wo0 : ((s == 1) ? wo1 : wo2);
            #pragma unroll
            for (int it = 0; it < 8; it++) {
                int idx = (it * 256 + tid) * 4;
                int co = idx >> 7, k = idx & 127;
                long src = wo + (long)(mh * 64 + co) * WROW + pass * 128 + k;
                uint2 h = *(const uint2*)&WHI[src];
                uint2 l = *(const uint2*)&WLO[src];
                uint32_t off = (uint32_t)(co * LDA + k) * 2;
                asm volatile("st.shared.v2.b32 [%0], {%1,%2};" :: "r"(sW_hi + off), "r"(h.x), "r"(h.y));
                asm volatile("st.shared.v2.b32 [%0], {%1,%2};" :: "r"(sW_lo + off), "r"(l.x), "r"(l.y));
            }
            __syncthreads();

            if (KPASS == 1) {
                #pragma unroll
                for (int mt = 0; mt < 2; mt++)
                    #pragma unroll
                    for (int nt = 0; nt < 4; nt++)
                        #pragma unroll
                        for (int e = 0; e < 4; e++) C[mt][nt][e] = 0.f;
            }

            #pragma unroll
            for (int kk = 0; kk < 8; kk++) {
                int k0 = kk * 16;
                uint32_t ah[2][4], al[2][4];
                #pragma unroll
                for (int mt = 0; mt < 2; mt++) {
                    uint32_t o = offW + (uint32_t)(mt * 16 * LDA + k0) * 2;
                    ldsm_x4(ah[mt], sW_hi + o);
                    ldsm_x4(al[mt], sW_lo + o);
                }
                uint32_t bh[2][4], bl[2][4];
                #pragma unroll
                for (int bt = 0; bt < 2; bt++) {
                    uint32_t o = offX + (uint32_t)(k0 * LDA + bt * 16) * 2;
                    ldsm_x4_t(bh[bt], sX_hi + o);
                    ldsm_x4_t(bl[bt], sX_lo + o);
                }
                #pragma unroll
                for (int mt = 0; mt < 2; mt++)
                    #pragma unroll
                    for (int nt = 0; nt < 4; nt++) {
                        uint32_t b0h = bh[nt >> 1][(nt & 1) * 2], b1h = bh[nt >> 1][(nt & 1) * 2 + 1];
                        uint32_t b0l = bl[nt >> 1][(nt & 1) * 2], b1l = bl[nt >> 1][(nt & 1) * 2 + 1];
                        mma_bf16(C[mt][nt], ah[mt], b0h, b1h);
                        mma_bf16(C[mt][nt], ah[mt], b0l, b1l);
                        mma_bf16(C[mt][nt], al[mt], b0h, b1h);
                    }
            }

            if (KPASS == 1 && STORE) {
                float* Yb = ((s == 0) ? Y0 : ((s == 1) ? Y1 : Y2)) + (long)bi * ystride;
                const int g = lane >> 2, i2 = (lane & 3) * 2;
                #pragma unroll
                for (int mt = 0; mt < 2; mt++) {
                    int row0 = mh * 64 + m0 + mt * 16 + g;
                    #pragma unroll
                    for (int nt = 0; nt < 4; nt++) {
                        int p = p0 + n0 + nt * 8 + i2;
                        float2 o0 = make_float2(C[mt][nt][0], C[mt][nt][1]);
                        float2 o1 = make_float2(C[mt][nt][2], C[mt][nt][3]);
                        if (GOUT) {
                            o0.x = gelu_f(o0.x); o0.y = gelu_f(o0.y);
                            o1.x = gelu_f(o1.x); o1.y = gelu_f(o1.y);
                        }
                        *(float2*)&Yb[(long)row0 * PP + p]       = o0;
                        *(float2*)&Yb[(long)(row0 + 8) * PP + p] = o1;
                    }
                }
            }
        }
    }

    if (POOL) {
        __syncthreads();
        float* ps = (float*)smem;
        float* pm = ps + 256;
        const int g = lane >> 2;
        #pragma unroll
        for (int mt = 0; mt < 2; mt++) {
            float s0 = 0.f, s1 = 0.f, m0v = -INFINITY, m1v = -INFINITY;
            #pragma unroll
            for (int nt = 0; nt < 4; nt++) {
                s0 += C[mt][nt][0] + C[mt][nt][1];
                m0v = fmaxf(m0v, fmaxf(C[mt][nt][0], C[mt][nt][1]));
                s1 += C[mt][nt][2] + C[mt][nt][3];
                m1v = fmaxf(m1v, fmaxf(C[mt][nt][2], C[mt][nt][3]));
            }
            #pragma unroll
            for (int o = 1; o <= 2; o <<= 1) {
                s0 += __shfl_xor_sync(0xffffffffu, s0, o);
                s1 += __shfl_xor_sync(0xffffffffu, s1, o);
                m0v = fmaxf(m0v, __shfl_xor_sync(0xffffffffu, m0v, o));
                m1v = fmaxf(m1v, __shfl_xor_sync(0xffffffffu, m1v, o));
            }
            if ((lane & 3) == 0) {
                int r0 = m0 + mt * 16 + g;
                ps[r0 * 4 + wn] = s0;       pm[r0 * 4 + wn] = m0v;
                ps[(r0 + 8) * 4 + wn] = s1; pm[(r0 + 8) * 4 + wn] = m1v;
            }
        }
        __syncthreads();
        if (tid < 64) {
            float s = ps[tid*4] + ps[tid*4+1] + ps[tid*4+2] + ps[tid*4+3];
            float m = fmaxf(fmaxf(pm[tid*4], pm[tid*4+1]), fmaxf(pm[tid*4+2], pm[tid*4+3]));
            long ch = (long)(bi * CC + mh * 64 + tid);
            psum[ch * NBX + blockIdx.x] = s;
            pmax[ch * NBX + blockIdx.x] = m;
        }
    }
}

// ---------------- multi-tensor depthwise 3x3 pad 1: 4x4 px/thread ----------------
template<int SQMASK, bool GSPLIT, bool QKSPLIT>
__global__ void __launch_bounds__(256) dwm_kernel(
    const float* __restrict__ x0, const float* __restrict__ x1, const float* __restrict__ x2,
    const float* __restrict__ w0, const float* __restrict__ w1, const float* __restrict__ w2,
    void* __restrict__ y0, void* __restrict__ y1, void* __restrict__ y2,
    float* __restrict__ sq0, float* __restrict__ sq1) {
    int i = blockIdx.x * 256 + threadIdx.x;
    int bc = blockIdx.y;
    int z  = blockIdx.z;
    const float* x = (z == 0) ? x0 : ((z == 1) ? x1 : x2);
    const float* w = (z == 0) ? w0 : ((z == 1) ? w1 : w2);
    void* yout     = (z == 0) ? y0 : ((z == 1) ? y1 : y2);
    const bool doSQ = (SQMASK >> z) & 1;

    int rq = i / 48, cg = i % 48;
    int y0r = rq * 4, xx = cg * 4;
    const float* xp = x + (size_t)bc * PP;
    const float* wc = w + (bc % CC) * 9;
    float kw[3][3];
    #pragma unroll
    for (int j = 0; j < 9; j++) kw[j/3][j%3] = wc[j];

    float4 c[6]; float lf[6], rt[6];
    #pragma unroll
    for (int r = 0; r < 6; r++) {
        int sy = y0r - 1 + r;
        bool ok = (unsigned)sy < HIMG;
        const float* row = xp + sy * WIMG + xx;
        c[r]  = ok ? *(const float4*)row : make_float4(0.f, 0.f, 0.f, 0.f);
        lf[r] = (ok && xx > 0) ? row[-1] : 0.f;
        rt[r] = (ok && xx + 4 < WIMG) ? row[4] : 0.f;
    }

    float4 a[4];
    #pragma unroll
    for (int r = 0; r < 4; r++) a[r] = make_float4(0.f, 0.f, 0.f, 0.f);
    #pragma unroll
    for (int ky = 0; ky < 3; ky++) {
        float k0 = kw[ky][0], k1 = kw[ky][1], k2 = kw[ky][2];
        #pragma unroll
        for (int r = 0; r < 4; r++) {
            float4 cc = c[r + ky]; float l = lf[r + ky], rr = rt[r + ky];
            a[r].x += k0*l    + k1*cc.x + k2*cc.y;
            a[r].y += k0*cc.x + k1*cc.y + k2*cc.z;
            a[r].z += k0*cc.y + k1*cc.z + k2*cc.w;
            a[r].w += k0*cc.z + k1*cc.w + k2*rr;
        }
    }

    const bool dosplit = GSPLIT || (QKSPLIT && z < 2);
    if (dosplit) {
        unsigned short* yh = (unsigned short*)yout;
        unsigned short* yl = yh + ELEMS;
        #pragma unroll
        for (int r = 0; r < 4; r++) {
            float gx = a[r].x, gy = a[r].y, gz = a[r].z, gw = a[r].w;
            if (GSPLIT) { gx = gelu_f(gx); gy = gelu_f(gy); gz = gelu_f(gz); gw = gelu_f(gw); }
            uint32_t h0, l0, h1, l1;
            split2(gx, gy, h0, l0);
            split2(gz, gw, h1, l1);
            size_t o = (size_t)bc * PP + (y0r + r) * WIMG + xx;
            *(uint2*)&yh[o] = make_uint2(h0, h1);
            *(uint2*)&yl[o] = make_uint2(l0, l1);
        }
    } else {
        float* yp = (float*)yout + (size_t)bc * PP;
        #pragma unroll
        for (int r = 0; r < 4; r++)
            *(float4*)&yp[(y0r + r) * WIMG + xx] = a[r];
    }

    if (SQMASK) {
        if (doSQ) {
            float s = 0.f;
            #pragma unroll
            for (int r = 0; r < 4; r++)
                s += a[r].x*a[r].x + a[r].y*a[r].y + a[r].z*a[r].z + a[r].w*a[r].w;
            __shared__ float red[256];
            red[threadIdx.x] = s; __syncthreads();
            for (int o = 128; o > 0; o >>= 1) {
                if (threadIdx.x < o) red[threadIdx.x] += red[threadIdx.x + o];
                __syncthreads();
            }
            if (threadIdx.x == 0) {
                float* sqp = (z == 0) ? sq0 : sq1;
                sqp[bc * NDW + blockIdx.x] = red[0];
            }
        }
    }
}

// ---------------- Gram partials via HMMA (pre-split q/k, copy staging, 3 CTAs/SM) ----------------
#define LDK 136
#define GT_BYTES (64*LDK*2)
#define GR_SMEM (4*GT_BYTES)
__global__ void __launch_bounds__(256, 3) gram_mma(const unsigned short* __restrict__ q,
                                                   const unsigned short* __restrict__ k,
                                                   float* __restrict__ part) {
    extern __shared__ __align__(16) char smem[];
    uint32_t sb = smem_u32(smem);
    uint32_t sQ_hi = sb, sQ_lo = sb + GT_BYTES;
    uint32_t sK_hi = sb + 2*GT_BYTES, sK_lo = sb + 3*GT_BYTES;

    const int tid = threadIdx.x;
    const int wid = tid >> 5, lane = tid & 31;
    const int ch = blockIdx.x, bn = blockIdx.y;
    const size_t base = (size_t)bn * HD * PP + (size_t)ch * CPX2;
    const unsigned short* qh = q + base;
    const unsigned short* ql = q + ELEMS + base;
    const unsigned short* kh = k + base;
    const unsigned short* kl = k + ELEMS + base;

    const int wm = wid & 1, wn = wid >> 1;
    const int m0 = wm * 32, n0 = wn * 16;
    const int ar = (lane & 7) + ((lane >> 3) & 1) * 8;
    const int ac = ((lane >> 4) & 1) * 8;
    const uint32_t offA = (uint32_t)((m0 + ar) * LDK + ac) * 2;
    const uint32_t offB = (uint32_t)((n0 + ar) * LDK + ac) * 2;

    float C[2][2][4];
    #pragma unroll
    for (int mt = 0; mt < 2; mt++)
        #pragma unroll
        for (int nt = 0; nt < 2; nt++)
            #pragma unroll
            for (int e = 0; e < 4; e++) C[mt][nt][e] = 0.f;

    for (int t = 0; t < CPX2 / 128; t++) {
        if (t > 0) __syncthreads();
        #pragma unroll
        for (int it = 0; it < 8; it++) {
            int idx = (it * 256 + tid) * 4;
            int r = idx >> 7, n = idx & 127;
            size_t src = (size_t)r * PP + t * 128 + n;
            uint2 h = *(const uint2*)&qh[src];
            uint2 l = *(const uint2*)&ql[src];
            uint32_t off = (uint32_t)(r * LDK + n) * 2;
            asm volatile("st.shared.v2.b32 [%0], {%1,%2};" :: "r"(sQ_hi + off), "r"(h.x), "r"(h.y));
            asm volatile("st.shared.v2.b32 [%0], {%1,%2};" :: "r"(sQ_lo + off), "r"(l.x), "r"(l.y));
        }
        #pragma unroll
        for (int it = 0; it < 8; it++) {
            int idx = (it * 256 + tid) * 4;
            int r = idx >> 7, n = idx & 127;
            size_t src = (size_t)r * PP + t * 128 + n;
            uint2 h = *(const uint2*)&kh[src];
            uint2 l = *(const uint2*)&kl[src];
            uint32_t off = (uint32_t)(r * LDK + n) * 2;
            asm volatile("st.shared.v2.b32 [%0], {%1,%2};" :: "r"(sK_hi + off), "r"(h.x), "r"(h.y));
            asm volatile("st.shared.v2.b32 [%0], {%1,%2};" :: "r"(sK_lo + off), "r"(l.x), "r"(l.y));
        }
        __syncthreads();

        #pragma unroll
        for (int kk = 0; kk < 8; kk++) {
            int k0 = kk * 16;
            uint32_t ah[2][4], al[2][4];
            #pragma unroll
            for (int mt = 0; mt < 2; mt++) {
                uint32_t o = offA + (uint32_t)(mt * 16 * LDK + k0) * 2;
                ldsm_x4(ah[mt], sQ_hi + o);
                ldsm_x4(al[mt], sQ_lo + o);
            }
            uint32_t bh[4], bl[4];
            ldsm_x4(bh, sK_hi + offB + (uint32_t)k0 * 2);
            ldsm_x4(bl, sK_lo + offB + (uint32_t)k0 * 2);
            #pragma unroll
            for (int mt = 0; mt < 2; mt++) {
                mma_bf16(C[mt][0], ah[mt], bh[0], bh[2]);
                mma_bf16(C[mt][1], ah[mt], bh[1], bh[3]);
                mma_bf16(C[mt][0], ah[mt], bl[0], bl[2]);
                mma_bf16(C[mt][1], ah[mt], bl[1], bl[3]);
                mma_bf16(C[mt][0], al[mt], bh[0], bh[2]);
                mma_bf16(C[mt][1], al[mt], bh[1], bh[3]);
            }
        }
    }

    float* pb = part + (((size_t)bn * NCH2 + ch) * HD) * HD;
    const int g = lane >> 2, i2 = (lane & 3) * 2;
    #pragma unroll
    for (int mt = 0; mt < 2; mt++) {
        int i = m0 + mt * 16 + g;
        #pragma unroll
        for (int nt = 0; nt < 2; nt++) {
            int j = n0 + nt * 8 + i2;
            pb[i * HD + j]       = C[mt][nt][0];
            pb[i * HD + j + 1]   = C[mt][nt][1];
            pb[(i + 8) * HD + j]     = C[mt][nt][2];
            pb[(i + 8) * HD + j + 1] = C[mt][nt][3];
        }
    }
}

// ---------------- norms (from dw sumsq partials) + reduce + softmax ----------------
// Grid: (BNH, 8). Each block handles 8 rows (i = blockIdx.y*8 + warp).
__global__ void attn_softmax(const float* __restrict__ part,
                             const float* __restrict__ sqq, const float* __restrict__ sqk,
                             const float* __restrict__ scale,
                             float* __restrict__ attnw_out, float* __restrict__ a) {
    __shared__ float nqS[HD], nkS[HD];
    int bn = blockIdx.x;
    int n = bn % NH;
    int tid = threadIdx.x;
    int warp = tid / 32, lane = tid % 32;

    if (tid < 128) {
        int i = tid & 63;
        const float* sp = (tid < 64) ? sqq : sqk;
        float s = 0.f;
        #pragma unroll
        for (int j = 0; j < NDW; j++) s += sp[(bn * HD + i) * NDW + j];
        float nv = fmaxf(sqrtf(s), 1e-12f);
        if (tid < 64) nqS[i] = nv; else nkS[i] = nv;
    }
    __syncthreads();

    float sc = scale[n];
    int i = blockIdx.y * 8 + warp;
    {
        float v[2];
        #pragma unroll
        for (int h = 0; h < 2; h++) {
            int j = lane + 32 * h;
            float s = 0.f;
            for (int ch = 0; ch < NCH2; ch++)
                s += part[(((size_t)bn * NCH2 + ch) * HD + i) * HD + j];
            s = s * sc / (nqS[i] * nkS[j]);
            attnw_out[((size_t)bn * HD + i) * HD + j] = s;
            v[h] = s;
        }
        float m = fmaxf(v[0], v[1]);
        #pragma unroll
        for (int o = 16; o; o >>= 1) m = fmaxf(m, __shfl_xor_sync(0xffffffffu, m, o));
        float e0 = expf(v[0] - m), e1 = expf(v[1] - m);
        float s = e0 + e1;
        #pragma unroll
        for (int o = 16; o; o >>= 1) s += __shfl_xor_sync(0xffffffffu, s, o);
        float inv = 1.0f / s;
        a[((size_t)bn * HD + i) * HD + lane]      = e0 * inv;
        a[((size_t)bn * HD + i) * HD + lane + 32] = e1 * inv;
    }
}

// ---------------- fused a@v + channel-LN ----------------
#define AV_SMEM (8192*4 + 128*132*4 + (2*1024 + 256)*4)
__global__ void __launch_bounds__(256) avln_kernel(
    const float* __restrict__ a, const float* __restrict__ v,
    const float* __restrict__ lnw, const float* __restrict__ lnb,
    float* __restrict__ t)
{
    extern __shared__ __align__(16) float dsm[];
    float* As = dsm;
    float* Vs = As + 8192;
    float* redS = Vs + 128*132;
    float* redQ = redS + 1024;
    float* muA  = redQ + 1024;
    float* rsA  = muA + 128;

    const int tid = threadIdx.x;
    const int bi = blockIdx.y;
    const int p0 = blockIdx.x * 128;

    const float* ab = a + (size_t)bi * 2 * 4096;
    #pragma unroll
    for (int it = 0; it < 8; it++) {
        int idx = (it * 256 + tid) * 4;
        *(float4*)&As[idx] = *(const float4*)&ab[idx];
    }
    const float* vb = v + (size_t)bi * CC * PP;
    #pragma unroll
    for (int it = 0; it < 16; it++) {
        int idx = it * 256 + tid;
        int row = idx >> 5, n4 = idx & 31;
        *(float4*)&Vs[row * 132 + n4 * 4] = *(const float4*)&vb[(size_t)row * PP + p0 + n4 * 4];
    }
    __syncthreads();

    const int px4 = tid & 31;
    const int cg = tid >> 5;
    const int h = cg >> 2;
    const int cbase = cg * 16;
    const float* Ah = As + h * 4096;

    float4 acc[16];
    #pragma unroll
    for (int cl = 0; cl < 16; cl++) acc[cl] = make_float4(0.f, 0.f, 0.f, 0.f);

    #pragma unroll
    for (int j4 = 0; j4 < 16; j4++) {
        float4 vv0 = *(float4*)&Vs[(h*64 + j4*4 + 0) * 132 + px4*4];
        float4 vv1 = *(float4*)&Vs[(h*64 + j4*4 + 1) * 132 + px4*4];
        float4 vv2 = *(float4*)&Vs[(h*64 + j4*4 + 2) * 132 + px4*4];
        float4 vv3 = *(float4*)&Vs[(h*64 + j4*4 + 3) * 132 + px4*4];
        #pragma unroll
        for (int cl = 0; cl < 16; cl++) {
            int i = (cbase + cl) & 63;
            float4 a4 = *(float4*)&Ah[i * 64 + j4 * 4];
            acc[cl].x += a4.x*vv0.x + a4.y*vv1.x + a4.z*vv2.x + a4.w*vv3.x;
            acc[cl].y += a4.x*vv0.y + a4.y*vv1.y + a4.z*vv2.y + a4.w*vv3.y;
            acc[cl].z += a4.x*vv0.z + a4.y*vv1.z + a4.z*vv2.z + a4.w*vv3.z;
            acc[cl].w += a4.x*vv0.w + a4.y*vv1.w + a4.z*vv2.w + a4.w*vv3.w;
        }
    }

    float4 s4 = make_float4(0.f,0.f,0.f,0.f), q4 = make_float4(0.f,0.f,0.f,0.f);
    #pragma unroll
    for (int cl = 0; cl < 16; cl++) {
        s4.x += acc[cl].x; s4.y += acc[cl].y; s4.z += acc[cl].z; s4.w += acc[cl].w;
        q4.x += acc[cl].x*acc[cl].x; q4.y += acc[cl].y*acc[cl].y;
        q4.z += acc[cl].z*acc[cl].z; q4.w += acc[cl].w*acc[cl].w;
    }
    *(float4*)&redS[cg * 128 + px4 * 4] = s4;
    *(float4*)&redQ[cg * 128 + px4 * 4] = q4;
    __syncthreads();
    if (tid < 128) {
        float s = 0.f, q2 = 0.f;
        #pragma unroll
        for (int g = 0; g < 8; g++) { s += redS[g * 128 + tid]; q2 += redQ[g * 128 + tid]; }
        float mu = s * (1.0f / 128.0f);
        float var = q2 * (1.0f / 128.0f) - mu * mu;
        muA[tid] = mu;
        rsA[tid] = rsqrtf(var + 1e-5f);
    }
    __syncthreads();

    float4 mu4 = *(float4*)&muA[px4 * 4];
    float4 rs4 = *(float4*)&rsA[px4 * 4];
    float* tb = t + (size_t)bi * CC * PP;
    #pragma unroll
    for (int cl = 0; cl < 16; cl++) {
        int c = cbase + cl;
        float w = __ldg(&lnw[c]), b = __ldg(&lnb[c]);
        float4 o;
        o.x = (acc[cl].x - mu4.x) * rs4.x * w + b;
        o.y = (acc[cl].y - mu4.y) * rs4.y * w + b;
        o.z = (acc[cl].z - mu4.z) * rs4.z * w + b;
        o.w = (acc[cl].w - mu4.w) * rs4.w * w + b;
        *(float4*)&tb[(size_t)c * PP + p0 + px4 * 4] = o;
    }
}

// ---------------- pool partial reduce + ChannelGate ----------------
__global__ void gate_pool_kernel(const float* __restrict__ psum, const float* __restrict__ pmax,
                                 const float* __restrict__ w1, const float* __restrict__ b1,
                                 const float* __restrict__ w2, const float* __restrict__ b2,
                                 float* __restrict__ out) {
    __shared__ float sa[CC], sm_[CC], ha[8], hm[8];
    int c = threadIdx.x;
    for (int b = 0; b < BB; b++) {
        float s = 0.f, m = -INFINITY;
        long base = (long)(b * CC + c) * NBX;
        for (int i = 0; i < NBX; i++) {
            s += psum[base + i];
            m = fmaxf(m, pmax[base + i]);
        }
        sa[c] = s * (1.0f / PP);
        sm_[c] = m;
        __syncthreads();
        if (c < 8) {
            float xa = b1[c], xm = b1[c];
            for (int cc = 0; cc < CC; cc++) {
                xa += w1[c*CC + cc] * sa[cc];
                xm += w1[c*CC + cc] * sm_[cc];
            }
            ha[c] = fmaxf(xa, 0.f);
            hm[c] = fmaxf(xm, 0.f);
        }
        __syncthreads();
        float xa = b2[c], xm = b2[c];
        #pragma unroll
        for (int j = 0; j < 8; j++) {
            xa += w2[c*8 + j] * ha[j];
            xm += w2[c*8 + j] * hm[j];
        }
        out[b*CC + c] = 1.0f / (1.0f + expf(-(xa + xm)));
        __syncthreads();
    }
}

// ---------------- host launch ----------------
static float* sym(const void* s) {
    void* p = nullptr;
    cudaGetSymbolAddress(&p, s);
    return (float*)p;
}

extern "C" void kernel_launch(void* const* d_in, const int* in_sizes, int n_in,
                              void* d_out, int out_size) {
    const float* x       = (const float*)d_in[0];
    const float* ln_in_w = (const float*)d_in[1];
    const float* ln_in_b = (const float*)d_in[2];
    const float* wq_pw   = (const float*)d_in[3];
    const float* wq_dw   = (const float*)d_in[4];
    const float* wk_pw   = (const float*)d_in[5];
    const float* wk_dw   = (const float*)d_in[6];
    const float* wv_pw   = (const float*)d_in[7];
    const float* wv_dw   = (const float*)d_in[8];
    const float* scale   = (const float*)d_in[9];
    const float* ln_o_w  = (const float*)d_in[10];
    const float* ln_o_b  = (const float*)d_in[11];
    const float* f1_pw   = (const float*)d_in[12];
    const float* f1_dw   = (const float*)d_in[13];
    const float* f2_pw   = (const float*)d_in[14];
    const float* f2_dw   = (const float*)d_in[15];
    const float* f_out   = (const float*)d_in[16];
    const float* g_w1    = (const float*)d_in[17];
    const float* g_b1    = (const float*)d_in[18];
    const float* g_w2    = (const float*)d_in[19];
    const float* g_b2    = (const float*)d_in[20];
    float* out = (float*)d_out;

    float* t  = sym(g_t);   float* t2 = sym(g_t2);  float* t3 = sym(g_t3);
    float* q  = sym(g_q);   float* k  = sym(g_k);   float* v  = sym(g_v);
    float* part = sym(g_part); float* a = sym(g_a);
    float* sqq = sym(g_sqq);   float* sqk = sym(g_sqk);
    float* psum = sym(g_psum); float* pmax = sym(g_pmax);
    unsigned short* whi = (unsigned short*)sym(g_whi);
    unsigned short* wlo = (unsigned short*)sym(g_wlo);

    auto qkv  = gemm_fused<1,3,true, false,false,false,true>;
    auto f1f2 = gemm_fused<1,2,false,false,true, false,true>;
    auto fout = gemm_fused<2,1,false,true, false,true, false>;
    cudaFuncSetAttribute(qkv,  cudaFuncAttributeMaxDynamicSharedMemorySize, MM_SMEM_LN);
    cudaFuncSetAttribute(f1f2, cudaFuncAttributeMaxDynamicSharedMemorySize, MM_SMEM);
    cudaFuncSetAttribute(fout, cudaFuncAttributeMaxDynamicSharedMemorySize, MM_SMEM);
    cudaFuncSetAttribute(gram_mma, cudaFuncAttributeMaxDynamicSharedMemorySize, GR_SMEM);
    cudaFuncSetAttribute(avln_kernel, cudaFuncAttributeMaxDynamicSharedMemorySize, AV_SMEM);

    const long SB = (long)CC * PP;
    dim3 gGrid(NBX, 2, BB);
    dim3 dwGrid3(NDW, BB*CC, 3);
    dim3 dwGrid2(NDW, BB*CC, 2);
    dim3 avGrid(NBX, BB);
    dim3 smGrid(BNH, 8);

    // 0) precompute weight hi/lo splits (single merged launch)
    wprep_all<<<(WTOT + 255)/256, 256>>>(wq_pw, wk_pw, wv_pw, f1_pw, f2_pw, f_out, whi, wlo);

    // 1) fused LN + QKV pointwise
    qkv<<<gGrid, 256, MM_SMEM_LN>>>(whi, wlo, OWQ, OWK, OWV, x, nullptr, SB,
                                    ln_in_w, ln_in_b, t, t2, t3, SB, nullptr, nullptr);
    // 2) depthwise q/k/v in ONE launch; q,k stored as split bf16 planes, v float
    dwm_kernel<3, false, true><<<dwGrid3, 256>>>(t, t2, t3, wq_dw, wk_dw, wv_dw,
                                                 q, k, v, sqq, sqk);
    // 3) Gram (HMMA, pre-split q/k, grid 384, 3 CTAs/SM) + softmax (64 blocks)
    gram_mma<<<dim3(NCH2, BNH), 256, GR_SMEM>>>((const unsigned short*)q,
                                                (const unsigned short*)k, part);
    attn_softmax<<<smGrid, 256>>>(part, sqq, sqk, scale, out + BB*CC, a);
    // 4) fused a@v + LN -> t
    avln_kernel<<<avGrid, 256, AV_SMEM>>>(a, v, ln_o_w, ln_o_b, t);
    // 5) fused f1+f2 pointwise (GELU out) -> t2, t3
    f1f2<<<gGrid, 256, MM_SMEM>>>(whi, wlo, OF1, OF2, 0, t, nullptr, SB,
                                  nullptr, nullptr, t2, t3, nullptr, SB, nullptr, nullptr);
    // 6) depthwise FFN branches in ONE launch -> gelu'd split bf16 planes
    dwm_kernel<0, true, false><<<dwGrid2, 256>>>(t2, t3, nullptr, f1_dw, f2_dw, nullptr,
                                                 q, k, nullptr, nullptr, nullptr);
    // 7) f_out (pre-split X, K=256) -> pool partials only
    fout<<<gGrid, 256, MM_SMEM>>>(whi, wlo, OFO, 0, 0, q, k, SB,
                                  nullptr, nullptr, nullptr, nullptr, nullptr, SB, psum, pmax);
    // 8) ChannelGate
    gate_pool_kernel<<<1, 128>>>(psum, pmax, g_w1, g_b1, g_w2, g_b2, out);
}